// round 8
// baseline (speedup 1.0000x reference)
#include <cuda_runtime.h>
#include <cuda_bf16.h>
#include <cstdint>

#define TT 8192
#define HH 2048
#define II 4096
#define EE 8
#define TK (TT*2)
#define MAXTILES 80
#define BK 16
#define BM 256

// ---- pool (402.9MB statics; ~1GB breaks module load — R4/R5 lesson) ----
#define OFF_HH  0ULL                 // h hi  bf16 [TK][II]   134MB
#define OFF_HL  134217728ULL         // h lo  bf16 [TK][II]   134MB
#define OFF_X   268435456ULL         // x hi  bf16 [TT][HH]    32MB (dead after GEMM1)
#define OFF_XL  301989888ULL         // x lo  bf16 [TT][HH]    32MB
#define OFF_OUT 268435456ULL         // out  fp32 [TK][HH]    134MB (reuses x region)
#define POOL_BYTES 402653184ULL

__device__ char g_pool[POOL_BYTES];
__device__ int   g_topi[TK];
__device__ float g_topw[TK];
__device__ int   g_rowtok[TK];
__device__ float g_rw[TK];
__device__ int   g_pos[TK];
__device__ int   g_counts[EE];
__device__ int   g_offsets[EE + 1];
__device__ int   g_fill[EE];
__device__ int   g_tile_e[MAXTILES];
__device__ int   g_tile_row[MAXTILES];
__device__ int   g_tile_rows[MAXTILES];
__device__ int   g_num_tiles;

// ---------------- PTX helpers (sm_80 baseline ISA) ----------------
__device__ __forceinline__ uint32_t smem_u32(const void* p) {
    uint32_t a;
    asm("{ .reg .u64 t; cvta.to.shared.u64 t, %1; cvt.u32.u64 %0, t; }"
        : "=r"(a) : "l"(p));
    return a;
}
__device__ __forceinline__ void cpasync16(uint32_t dst, const void* src) {
    asm volatile("cp.async.cg.shared.global [%0], [%1], 16;"
                 :: "r"(dst), "l"(src) : "memory");
}
__device__ __forceinline__ void ldmx4(uint32_t* r, uint32_t addr) {
    asm volatile("ldmatrix.sync.aligned.m8n8.x4.shared.b16 {%0,%1,%2,%3}, [%4];"
                 : "=r"(r[0]), "=r"(r[1]), "=r"(r[2]), "=r"(r[3]) : "r"(addr));
}
__device__ __forceinline__ void ldmx4t(uint32_t* r, uint32_t addr) {
    asm volatile("ldmatrix.sync.aligned.m8n8.x4.trans.shared.b16 {%0,%1,%2,%3}, [%4];"
                 : "=r"(r[0]), "=r"(r[1]), "=r"(r[2]), "=r"(r[3]) : "r"(addr));
}
__device__ __forceinline__ void mma16816(float* d, const uint32_t* a,
                                         const uint32_t* b) {
    asm volatile(
        "mma.sync.aligned.m16n8k16.row.col.f32.bf16.bf16.f32 "
        "{%0,%1,%2,%3}, {%4,%5,%6,%7}, {%8,%9}, {%0,%1,%2,%3};"
        : "+f"(d[0]), "+f"(d[1]), "+f"(d[2]), "+f"(d[3])
        : "r"(a[0]), "r"(a[1]), "r"(a[2]), "r"(a[3]), "r"(b[0]), "r"(b[1]));
}

// ---------------- small kernels (proven) ----------------
__global__ void init_kernel() {
    int t = threadIdx.x;
    if (t < EE) { g_counts[t] = 0; g_fill[t] = 0; }
    if (t == 0) g_num_tiles = 0;
}

__global__ void router_kernel(const float* __restrict__ x,
                              const float* __restrict__ rw) {
    int warp = (blockIdx.x * blockDim.x + threadIdx.x) >> 5;
    int lane = threadIdx.x & 31;
    if (warp >= TT) return;
    const float* xr = x + (size_t)warp * HH;
    float acc[EE];
#pragma unroll
    for (int e = 0; e < EE; e++) acc[e] = 0.f;
    for (int i = lane * 4; i < HH; i += 128) {
        float4 xv = *(const float4*)&xr[i];
#pragma unroll
        for (int e = 0; e < EE; e++) {
            float4 wv = *(const float4*)&rw[e * HH + i];
            acc[e] += xv.x * wv.x + xv.y * wv.y + xv.z * wv.z + xv.w * wv.w;
        }
    }
#pragma unroll
    for (int e = 0; e < EE; e++)
#pragma unroll
        for (int off = 16; off; off >>= 1)
            acc[e] += __shfl_xor_sync(0xffffffffu, acc[e], off);
    if (lane == 0) {
        float mx = acc[0];
#pragma unroll
        for (int e = 1; e < EE; e++) mx = fmaxf(mx, acc[e]);
        float p[EE], s = 0.f;
#pragma unroll
        for (int e = 0; e < EE; e++) { p[e] = expf(acc[e] - mx); s += p[e]; }
        float inv = 1.f / s;
        int i1 = 0; float v1 = p[0];
#pragma unroll
        for (int e = 1; e < EE; e++) if (p[e] > v1) { v1 = p[e]; i1 = e; }
        int i2 = -1; float v2 = -1.f;
#pragma unroll
        for (int e = 0; e < EE; e++)
            if (e != i1 && p[e] > v2) { v2 = p[e]; i2 = e; }
        g_topi[warp * 2]     = i1; g_topw[warp * 2]     = v1 * inv;
        g_topi[warp * 2 + 1] = i2; g_topw[warp * 2 + 1] = v2 * inv;
        atomicAdd(&g_counts[i1], 1);
        atomicAdd(&g_counts[i2], 1);
    }
}

__global__ void build_kernel(float* d_out, long long out_size) {
    if (threadIdx.x != 0) return;
    int off = 0;
    for (int e = 0; e < EE; e++) { g_offsets[e] = off; off += g_counts[e]; }
    g_offsets[EE] = off;
    int nt = 0;
    for (int e = 0; e < EE; e++) {
        int n = g_counts[e];
        for (int j = 0; j < n; j += BM) {
            g_tile_e[nt]    = e;
            g_tile_row[nt]  = g_offsets[e] + j;
            g_tile_rows[nt] = (n - j < BM) ? (n - j) : BM;
            nt++;
        }
    }
    g_num_tiles = nt;
    long long base = (long long)TT * HH;
    long long extra = out_size - base;
    for (long long i = 0; i < extra; i++)
        d_out[base + i] = (i < EE) ? (float)g_counts[i] : 0.f;
}

__global__ void scatter_kernel() {
    int i = blockIdx.x * blockDim.x + threadIdx.x;
    if (i >= TK) return;
    int e = g_topi[i];
    int p = g_offsets[e] + atomicAdd(&g_fill[e], 1);
    g_rowtok[p] = i >> 1;
    g_rw[p]     = g_topw[i];
    g_pos[i]    = p;
}

// ---------------- x -> bf16 hi/lo split ----------------
__global__ void convert_x_kernel(const float* __restrict__ x) {
    int i = blockIdx.x * blockDim.x + threadIdx.x;
    float4 v = ((const float4*)x)[i];
    __nv_bfloat162 h0, h1, l0, l1;
    h0.x = __float2bfloat16(v.x); l0.x = __float2bfloat16(v.x - __bfloat162float(h0.x));
    h0.y = __float2bfloat16(v.y); l0.y = __float2bfloat16(v.y - __bfloat162float(h0.y));
    h1.x = __float2bfloat16(v.z); l1.x = __float2bfloat16(v.z - __bfloat162float(h1.x));
    h1.y = __float2bfloat16(v.w); l1.y = __float2bfloat16(v.w - __bfloat162float(h1.y));
    __nv_bfloat162* oh = (__nv_bfloat162*)(g_pool + OFF_X);
    __nv_bfloat162* ol = (__nv_bfloat162*)(g_pool + OFF_XL);
    oh[i * 2] = h0; oh[i * 2 + 1] = h1;
    ol[i * 2] = l0; ol[i * 2 + 1] = l1;
}

// ---------------- grouped GEMM: 256x128 tile, mma.sync bf16x3 --------------
// MODE 0: h = gelu(xs @ w1)   MODE 1: out = rw*(h @ w2)
// Warp grid 4(m) x 2(n); warp tile 64x64.
// A smem: [stage][hi 8192 | lo 8192], row pitch 32B (256 rows).
// B smem: [stage][hi 4096 | lo 4096], row pitch 256B, 16B-seg XOR swizzle.
template <int MODE>
__global__ __launch_bounds__(256, 1) void moe_mma_kernel(const float* __restrict__ W) {
    const int KLEN = MODE ? II : HH;
    const int BROW = MODE ? HH : II;
    const int NC = KLEN / BK;
    int tile = blockIdx.y;
    if (tile >= g_num_tiles) return;
    const int e = g_tile_e[tile], row0 = g_tile_row[tile], rows = g_tile_rows[tile];
    const int n0 = blockIdx.x * 128;
    const int tid = threadIdx.x, wid = tid >> 5, lane = tid & 31;
    const int wm = wid >> 1, wn = wid & 1;     // warp tile 64(m) x 64(n)

    __shared__ __align__(128) char A_sm[2][16384];
    __shared__ __align__(128) char B_sm[2][8192];
    uint32_t sbA = smem_u32(A_sm);
    uint32_t sbB = smem_u32(B_sm);

    const __nv_bfloat16* Ahg = (const __nv_bfloat16*)(g_pool + (MODE ? OFF_HH : OFF_X));
    const __nv_bfloat16* Alg = (const __nv_bfloat16*)(g_pool + (MODE ? OFF_HL : OFF_XL));
    const float* We = W + (size_t)e * KLEN * BROW;

    // thread tid owns A row tid (clamped for remainder tiles)
    const int arow = (tid < rows) ? tid : (rows - 1);
    const size_t abase = MODE ? (size_t)(row0 + arow) * II
                              : (size_t)g_rowtok[row0 + arow] * HH;

    auto load_A = [&](int st, int k0) {
        uint32_t so = sbA + (uint32_t)(st * 16384 + tid * 32);
        const char* ph = (const char*)(Ahg + abase + k0);
        const char* pl = (const char*)(Alg + abase + k0);
        cpasync16(so,            ph);
        cpasync16(so + 16,       ph + 16);
        cpasync16(so + 8192,     pl);
        cpasync16(so + 8192 + 16, pl + 16);
        asm volatile("cp.async.commit_group;" ::: "memory");
    };

    // B reg staging: thread t: k = t>>4 (0..15), seg = t&15 (16B col-seg)
    const int bk_r = tid >> 4, bseg = tid & 15;
    const float* Bsrc = We + (size_t)bk_r * BROW + n0 + bseg * 8;
    float4 br0, br1;
    auto ldg_B = [&](int k0) {
        const float4* s = (const float4*)(Bsrc + (size_t)k0 * BROW);
        br0 = s[0]; br1 = s[1];
    };
    const uint32_t boff = (uint32_t)(bk_r * 256 + ((bseg ^ (bk_r & 7)) * 16));
    auto sts_B = [&](int st) {
        float vs[8] = {br0.x, br0.y, br0.z, br0.w, br1.x, br1.y, br1.z, br1.w};
        __align__(16) __nv_bfloat16 hb[8], lb[8];
#pragma unroll
        for (int i = 0; i < 8; i++) {
            hb[i] = __float2bfloat16(vs[i]);
            lb[i] = __float2bfloat16(vs[i] - __bfloat162float(hb[i]));
        }
        *(uint4*)(B_sm[st] + boff) = *(uint4*)hb;
        *(uint4*)(B_sm[st] + 4096 + boff) = *(uint4*)lb;
    };

    float acc[4][8][4];
#pragma unroll
    for (int a = 0; a < 4; a++)
#pragma unroll
        for (int b = 0; b < 8; b++)
#pragma unroll
            for (int c = 0; c < 4; c++) acc[a][b][c] = 0.f;

    ldg_B(0);
    load_A(0, 0);

    for (int ch = 0; ch < NC; ch++) {
        int st = ch & 1;
        sts_B(st);                               // B(ch) regs -> smem
        if (ch + 1 < NC) ldg_B((ch + 1) * BK);   // prefetch B(ch+1)
        asm volatile("cp.async.wait_group 0;" ::: "memory");  // A(ch) resident
        __syncthreads();
        if (ch + 1 < NC) load_A(st ^ 1, (ch + 1) * BK);

        uint32_t Afh[4][4], Afl[4][4], Bfh[4][4], Bfl[4][4];
#pragma unroll
        for (int mi = 0; mi < 4; mi++) {
            uint32_t ad = sbA + (uint32_t)(st * 16384 +
                (wm * 64 + mi * 16 + (lane & 15)) * 32 + ((lane >> 4) & 1) * 16);
            ldmx4(Afh[mi], ad);
            ldmx4(Afl[mi], ad + 8192);
        }
#pragma unroll
        for (int np = 0; np < 4; np++) {
            int krow = ((lane >> 3) & 1) * 8 + (lane & 7);
            int ncol = wn * 64 + np * 16 + ((lane >> 4) & 1) * 8;
            int seg = ncol >> 3;
            uint32_t bd = sbB + (uint32_t)(st * 8192 + krow * 256 +
                                           ((seg ^ (krow & 7)) * 16));
            ldmx4t(Bfh[np], bd);
            ldmx4t(Bfl[np], bd + 4096);
        }
#pragma unroll
        for (int mi = 0; mi < 4; mi++)
#pragma unroll
            for (int np = 0; np < 4; np++)
#pragma unroll
                for (int j = 0; j < 2; j++) {
                    mma16816(acc[mi][np * 2 + j], Afh[mi], &Bfh[np][j * 2]);
                    mma16816(acc[mi][np * 2 + j], Afl[mi], &Bfh[np][j * 2]);
                    mma16816(acc[mi][np * 2 + j], Afh[mi], &Bfl[np][j * 2]);
                }
        __syncthreads();   // B stage st consumed before overwrite at ch+2
    }

    // ---------------- epilogue ----------------
    __nv_bfloat16* hh = (__nv_bfloat16*)(g_pool + OFF_HH);
    __nv_bfloat16* hl = (__nv_bfloat16*)(g_pool + OFF_HL);
    float* outp = (float*)(g_pool + OFF_OUT);
#pragma unroll
    for (int mi = 0; mi < 4; mi++) {
#pragma unroll
        for (int hr = 0; hr < 2; hr++) {
            int mloc = wm * 64 + mi * 16 + hr * 8 + (lane >> 2);
            if (mloc >= rows) continue;
            if (MODE == 0) {
                size_t base = (size_t)(row0 + mloc) * II + n0 + wn * 64 + (lane & 3) * 2;
#pragma unroll
                for (int ni = 0; ni < 8; ni++) {
                    float v0 = acc[mi][ni][hr * 2 + 0];
                    float v1 = acc[mi][ni][hr * 2 + 1];
                    float t0 = 0.7978845608028654f * (v0 + 0.044715f * v0 * v0 * v0);
                    float t1 = 0.7978845608028654f * (v1 + 0.044715f * v1 * v1 * v1);
                    float g0 = 0.5f * v0 * (1.f + tanhf(t0));
                    float g1 = 0.5f * v1 * (1.f + tanhf(t1));
                    __nv_bfloat162 h, l;
                    h.x = __float2bfloat16(g0);
                    l.x = __float2bfloat16(g0 - __bfloat162float(h.x));
                    h.y = __float2bfloat16(g1);
                    l.y = __float2bfloat16(g1 - __bfloat162float(h.y));
                    *(__nv_bfloat162*)&hh[base + ni * 8] = h;
                    *(__nv_bfloat162*)&hl[base + ni * 8] = l;
                }
            } else {
                float w = g_rw[row0 + mloc];
                size_t base = (size_t)(row0 + mloc) * HH + n0 + wn * 64 + (lane & 3) * 2;
#pragma unroll
                for (int ni = 0; ni < 8; ni++) {
                    float2 o;
                    o.x = acc[mi][ni][hr * 2 + 0] * w;
                    o.y = acc[mi][ni][hr * 2 + 1] * w;
                    *(float2*)&outp[base + ni * 8] = o;
                }
            }
        }
    }
}

// ---------------- combine ----------------
__global__ void combine_kernel(float* __restrict__ y) {
    int idx = blockIdx.x * blockDim.x + threadIdx.x;
    int t = idx >> 9, c4 = idx & 511;
    const float4* o = (const float4*)(g_pool + OFF_OUT);
    int p0 = g_pos[t * 2], p1 = g_pos[t * 2 + 1];
    float4 v0 = o[(size_t)p0 * 512 + c4];
    float4 v1 = o[(size_t)p1 * 512 + c4];
    float4 r;
    r.x = v0.x + v1.x; r.y = v0.y + v1.y;
    r.z = v0.z + v1.z; r.w = v0.w + v1.w;
    ((float4*)y)[idx] = r;
}

// ---------------- launch ----------------
extern "C" void kernel_launch(void* const* d_in, const int* in_sizes, int n_in,
                              void* d_out, int out_size) {
    const float* x  = (const float*)d_in[0];
    const float* rw = (const float*)d_in[1];
    const float* w1 = (const float*)d_in[2];
    const float* w2 = (const float*)d_in[3];
    float* y = (float*)d_out;

    init_kernel<<<1, 32>>>();
    router_kernel<<<TT / 8, 256>>>(x, rw);
    build_kernel<<<1, 32>>>(y, (long long)out_size);
    scatter_kernel<<<TK / 256, 256>>>();
    convert_x_kernel<<<(TT * HH / 4) / 256, 256>>>(x);

    moe_mma_kernel<0><<<dim3(II / 128, 72), 256>>>(w1);
    moe_mma_kernel<1><<<dim3(HH / 128, 72), 256>>>(w2);

    combine_kernel<<<(TT * HH / 4) / 256, 256>>>(y);
}

// round 10
// speedup vs baseline: 1.1303x; 1.1303x over previous
#include <cuda_runtime.h>
#include <cuda_bf16.h>
#include <cstdint>

#define TT 8192
#define HH 2048
#define II 4096
#define EE 8
#define TK (TT*2)
#define MAXTILES 144
#define BM 128
#define BK 32

// smem layout (dynamic, 73728B): A[st]: st*20480 (hi 10240 | lo 10240), pitch 80
//                                B[st]: 40960 + st*16384 (hi 8192 | lo 8192), pitch 256 swz
#define ASTG 20480
#define BBASE 40960
#define BSTG 16384
#define SMEM_DYN 73728

// ---- pool (402.9MB statics; ~1GB breaks module load — R4/R5 lesson) ----
#define OFF_HH  0ULL
#define OFF_HL  134217728ULL
#define OFF_X   268435456ULL
#define OFF_XL  301989888ULL
#define OFF_OUT 268435456ULL
#define POOL_BYTES 402653184ULL

__device__ char g_pool[POOL_BYTES];
__device__ int   g_topi[TK];
__device__ float g_topw[TK];
__device__ int   g_rowtok[TK];
__device__ float g_rw[TK];
__device__ int   g_pos[TK];
__device__ int   g_counts[EE];
__device__ int   g_offsets[EE + 1];
__device__ int   g_fill[EE];
__device__ int   g_tile_e[MAXTILES];
__device__ int   g_tile_row[MAXTILES];
__device__ int   g_tile_rows[MAXTILES];
__device__ int   g_num_tiles;

// ---------------- PTX helpers (sm_80 baseline ISA) ----------------
__device__ __forceinline__ uint32_t smem_u32(const void* p) {
    uint32_t a;
    asm("{ .reg .u64 t; cvta.to.shared.u64 t, %1; cvt.u32.u64 %0, t; }"
        : "=r"(a) : "l"(p));
    return a;
}
__device__ __forceinline__ void cpasync16(uint32_t dst, const void* src) {
    asm volatile("cp.async.cg.shared.global [%0], [%1], 16;"
                 :: "r"(dst), "l"(src) : "memory");
}
__device__ __forceinline__ void ldmx4(uint32_t* r, uint32_t addr) {
    asm volatile("ldmatrix.sync.aligned.m8n8.x4.shared.b16 {%0,%1,%2,%3}, [%4];"
                 : "=r"(r[0]), "=r"(r[1]), "=r"(r[2]), "=r"(r[3]) : "r"(addr));
}
__device__ __forceinline__ void ldmx4t(uint32_t* r, uint32_t addr) {
    asm volatile("ldmatrix.sync.aligned.m8n8.x4.trans.shared.b16 {%0,%1,%2,%3}, [%4];"
                 : "=r"(r[0]), "=r"(r[1]), "=r"(r[2]), "=r"(r[3]) : "r"(addr));
}
__device__ __forceinline__ void mma16816(float* d, const uint32_t* a,
                                         const uint32_t* b) {
    asm volatile(
        "mma.sync.aligned.m16n8k16.row.col.f32.bf16.bf16.f32 "
        "{%0,%1,%2,%3}, {%4,%5,%6,%7}, {%8,%9}, {%0,%1,%2,%3};"
        : "+f"(d[0]), "+f"(d[1]), "+f"(d[2]), "+f"(d[3])
        : "r"(a[0]), "r"(a[1]), "r"(a[2]), "r"(a[3]), "r"(b[0]), "r"(b[1]));
}

// ---------------- small kernels (proven) ----------------
__global__ void init_kernel() {
    int t = threadIdx.x;
    if (t < EE) { g_counts[t] = 0; g_fill[t] = 0; }
    if (t == 0) g_num_tiles = 0;
}

__global__ void router_kernel(const float* __restrict__ x,
                              const float* __restrict__ rw) {
    int warp = (blockIdx.x * blockDim.x + threadIdx.x) >> 5;
    int lane = threadIdx.x & 31;
    if (warp >= TT) return;
    const float* xr = x + (size_t)warp * HH;
    float acc[EE];
#pragma unroll
    for (int e = 0; e < EE; e++) acc[e] = 0.f;
    for (int i = lane * 4; i < HH; i += 128) {
        float4 xv = *(const float4*)&xr[i];
#pragma unroll
        for (int e = 0; e < EE; e++) {
            float4 wv = *(const float4*)&rw[e * HH + i];
            acc[e] += xv.x * wv.x + xv.y * wv.y + xv.z * wv.z + xv.w * wv.w;
        }
    }
#pragma unroll
    for (int e = 0; e < EE; e++)
#pragma unroll
        for (int off = 16; off; off >>= 1)
            acc[e] += __shfl_xor_sync(0xffffffffu, acc[e], off);
    if (lane == 0) {
        float mx = acc[0];
#pragma unroll
        for (int e = 1; e < EE; e++) mx = fmaxf(mx, acc[e]);
        float p[EE], s = 0.f;
#pragma unroll
        for (int e = 0; e < EE; e++) { p[e] = expf(acc[e] - mx); s += p[e]; }
        float inv = 1.f / s;
        int i1 = 0; float v1 = p[0];
#pragma unroll
        for (int e = 1; e < EE; e++) if (p[e] > v1) { v1 = p[e]; i1 = e; }
        int i2 = -1; float v2 = -1.f;
#pragma unroll
        for (int e = 0; e < EE; e++)
            if (e != i1 && p[e] > v2) { v2 = p[e]; i2 = e; }
        g_topi[warp * 2]     = i1; g_topw[warp * 2]     = v1 * inv;
        g_topi[warp * 2 + 1] = i2; g_topw[warp * 2 + 1] = v2 * inv;
        atomicAdd(&g_counts[i1], 1);
        atomicAdd(&g_counts[i2], 1);
    }
}

__global__ void build_kernel(float* d_out, long long out_size) {
    if (threadIdx.x != 0) return;
    int off = 0;
    for (int e = 0; e < EE; e++) { g_offsets[e] = off; off += g_counts[e]; }
    g_offsets[EE] = off;
    int nt = 0;
    for (int e = 0; e < EE; e++) {
        int n = g_counts[e];
        for (int j = 0; j < n; j += BM) {
            g_tile_e[nt]    = e;
            g_tile_row[nt]  = g_offsets[e] + j;
            g_tile_rows[nt] = (n - j < BM) ? (n - j) : BM;
            nt++;
        }
    }
    g_num_tiles = nt;
    long long base = (long long)TT * HH;
    long long extra = out_size - base;
    for (long long i = 0; i < extra; i++)
        d_out[base + i] = (i < EE) ? (float)g_counts[i] : 0.f;
}

__global__ void scatter_kernel() {
    int i = blockIdx.x * blockDim.x + threadIdx.x;
    if (i >= TK) return;
    int e = g_topi[i];
    int p = g_offsets[e] + atomicAdd(&g_fill[e], 1);
    g_rowtok[p] = i >> 1;
    g_rw[p]     = g_topw[i];
    g_pos[i]    = p;
}

// ---------------- x -> bf16 hi/lo split ----------------
__global__ void convert_x_kernel(const float* __restrict__ x) {
    int i = blockIdx.x * blockDim.x + threadIdx.x;
    float4 v = ((const float4*)x)[i];
    __nv_bfloat162 h0, h1, l0, l1;
    h0.x = __float2bfloat16(v.x); l0.x = __float2bfloat16(v.x - __bfloat162float(h0.x));
    h0.y = __float2bfloat16(v.y); l0.y = __float2bfloat16(v.y - __bfloat162float(h0.y));
    h1.x = __float2bfloat16(v.z); l1.x = __float2bfloat16(v.z - __bfloat162float(h1.x));
    h1.y = __float2bfloat16(v.w); l1.y = __float2bfloat16(v.w - __bfloat162float(h1.y));
    __nv_bfloat162* oh = (__nv_bfloat162*)(g_pool + OFF_X);
    __nv_bfloat162* ol = (__nv_bfloat162*)(g_pool + OFF_XL);
    oh[i * 2] = h0; oh[i * 2 + 1] = h1;
    ol[i * 2] = l0; ol[i * 2 + 1] = l1;
}

// ---------------- grouped GEMM: 128x128, BK=32, 1 sync/chunk ---------------
// MODE 0: h = gelu(xs @ w1)   MODE 1: out = rw*(h @ w2)
// Warp grid 2(m) x 4(n), warp tile 64x32 (R7-proven fragment mapping).
template <int MODE>
__global__ __launch_bounds__(256, 2) void moe_mma_kernel(const float* __restrict__ W) {
    const int KLEN = MODE ? II : HH;
    const int BROW = MODE ? HH : II;
    const int NC = KLEN / BK;
    int tile = blockIdx.y;
    if (tile >= g_num_tiles) return;
    const int e = g_tile_e[tile], row0 = g_tile_row[tile], rows = g_tile_rows[tile];
    const int n0 = blockIdx.x * 128;
    const int tid = threadIdx.x, wid = tid >> 5, lane = tid & 31;
    const int wm = wid & 1, wn = wid >> 1;   // 64(m) x 32(n) warp tile

    extern __shared__ __align__(128) char dsm[];
    uint32_t sb = smem_u32(dsm);

    const __nv_bfloat16* Ahg = (const __nv_bfloat16*)(g_pool + (MODE ? OFF_HH : OFF_X));
    const __nv_bfloat16* Alg = (const __nv_bfloat16*)(g_pool + (MODE ? OFF_HL : OFF_XL));
    const float* We = W + (size_t)e * KLEN * BROW;

    // A: thread pair per row; 80B pitch (bank-skewed)
    const int arow_i = tid >> 1, ahalf = tid & 1;
    const int arow = (arow_i < rows) ? arow_i : (rows - 1);
    const size_t abase = MODE ? (size_t)(row0 + arow) * II
                              : (size_t)g_rowtok[row0 + arow] * HH;
    auto load_A = [&](int st, int k0) {
        uint32_t so = sb + (uint32_t)(st * ASTG + arow_i * 80 + ahalf * 32);
        const char* ph = (const char*)(Ahg + abase + k0 + ahalf * 16);
        const char* pl = (const char*)(Alg + abase + k0 + ahalf * 16);
        cpasync16(so,              ph);
        cpasync16(so + 16,         ph + 16);
        cpasync16(so + 10240,      pl);
        cpasync16(so + 10240 + 16, pl + 16);
        asm volatile("cp.async.commit_group;" ::: "memory");
    };

    // B: thread owns row k=tid>>3 (0..31), segs bs0 and bs0+1 (16 floats)
    const int bk = tid >> 3, bs0 = (tid & 7) * 2;
    const float* Bsrc = We + (size_t)bk * BROW + n0 + bs0 * 8;
    float4 br0, br1, br2, br3;
    auto ldg_B = [&](int k0) {
        const float4* p = (const float4*)(Bsrc + (size_t)k0 * BROW);
        br0 = p[0]; br1 = p[1]; br2 = p[2]; br3 = p[3];
    };
    const uint32_t bo0 = (uint32_t)(bk * 256 + ((bs0 ^ (bk & 7)) * 16));
    const uint32_t bo1 = (uint32_t)(bk * 256 + (((bs0 + 1) ^ (bk & 7)) * 16));
    auto sts_B = [&](int st) {
        float vs[16] = {br0.x, br0.y, br0.z, br0.w, br1.x, br1.y, br1.z, br1.w,
                        br2.x, br2.y, br2.z, br2.w, br3.x, br3.y, br3.z, br3.w};
        __align__(16) __nv_bfloat16 hb[16], lb[16];
#pragma unroll
        for (int i = 0; i < 16; i++) {
            hb[i] = __float2bfloat16(vs[i]);
            lb[i] = __float2bfloat16(vs[i] - __bfloat162float(hb[i]));
        }
        char* bb = dsm + BBASE + st * BSTG;
        *(uint4*)(bb + bo0)        = *(uint4*)hb;
        *(uint4*)(bb + bo1)        = *(uint4*)(hb + 8);
        *(uint4*)(bb + 8192 + bo0) = *(uint4*)lb;
        *(uint4*)(bb + 8192 + bo1) = *(uint4*)(lb + 8);
    };

    float acc[4][4][4];
#pragma unroll
    for (int a = 0; a < 4; a++)
#pragma unroll
        for (int b = 0; b < 4; b++)
#pragma unroll
            for (int c = 0; c < 4; c++) acc[a][b][c] = 0.f;

    // prologue: B(0)->smem st0, A(0) in flight, B(1) in regs
    ldg_B(0);
    load_A(0, 0);
    sts_B(0);
    ldg_B(BK);
    asm volatile("cp.async.wait_group 0;" ::: "memory");
    __syncthreads();

    for (int ch = 0; ch < NC; ch++) {
        int st = ch & 1;
        if (ch + 1 < NC) {
            load_A(st ^ 1, (ch + 1) * BK);   // commits one group
            sts_B(st ^ 1);                    // regs hold B(ch+1)
        }
        if (ch + 2 < NC) ldg_B((ch + 2) * BK);
        if (ch + 1 < NC) asm volatile("cp.async.wait_group 1;" ::: "memory");
        else             asm volatile("cp.async.wait_group 0;" ::: "memory");

        uint32_t Ast = sb + (uint32_t)(st * ASTG);
        uint32_t Bst = sb + (uint32_t)(BBASE + st * BSTG);
#pragma unroll
        for (int ksub = 0; ksub < 2; ksub++) {
            uint32_t Afh[4][4], Afl[4][4], Bfh[8], Bfl[8];
#pragma unroll
            for (int mi = 0; mi < 4; mi++) {
                uint32_t ad = Ast + (uint32_t)(
                    (wm * 64 + mi * 16 + (lane & 15)) * 80 +
                    ksub * 32 + ((lane >> 4) & 1) * 16);
                ldmx4(Afh[mi], ad);
                ldmx4(Afl[mi], ad + 10240);
            }
#pragma unroll
            for (int np = 0; np < 2; np++) {
                int krow = ksub * 16 + ((lane >> 3) & 1) * 8 + (lane & 7);
                int ncol = wn * 32 + np * 16 + ((lane >> 4) & 1) * 8;
                int seg = ncol >> 3;
                uint32_t bd = Bst + (uint32_t)(krow * 256 +
                                               ((seg ^ (krow & 7)) * 16));
                ldmx4t(&Bfh[np * 4], bd);
                ldmx4t(&Bfl[np * 4], bd + 8192);
            }
#pragma unroll
            for (int mi = 0; mi < 4; mi++)
#pragma unroll
                for (int ni = 0; ni < 4; ni++) {
                    mma16816(acc[mi][ni], Afh[mi], &Bfh[ni * 2]);
                    mma16816(acc[mi][ni], Afl[mi], &Bfh[ni * 2]);
                    mma16816(acc[mi][ni], Afh[mi], &Bfl[ni * 2]);
                }
        }
        __syncthreads();
    }

    // ---------------- epilogue (R7-proven) ----------------
    __nv_bfloat16* hh = (__nv_bfloat16*)(g_pool + OFF_HH);
    __nv_bfloat16* hl = (__nv_bfloat16*)(g_pool + OFF_HL);
    float* outp = (float*)(g_pool + OFF_OUT);
#pragma unroll
    for (int mi = 0; mi < 4; mi++) {
#pragma unroll
        for (int hr = 0; hr < 2; hr++) {
            int mloc = wm * 64 + mi * 16 + hr * 8 + (lane >> 2);
            if (mloc >= rows) continue;
            if (MODE == 0) {
                size_t base = (size_t)(row0 + mloc) * II + n0 + wn * 32 + (lane & 3) * 2;
#pragma unroll
                for (int ni = 0; ni < 4; ni++) {
                    float v0 = acc[mi][ni][hr * 2 + 0];
                    float v1 = acc[mi][ni][hr * 2 + 1];
                    float t0 = 0.7978845608028654f * (v0 + 0.044715f * v0 * v0 * v0);
                    float t1 = 0.7978845608028654f * (v1 + 0.044715f * v1 * v1 * v1);
                    float g0 = 0.5f * v0 * (1.f + tanhf(t0));
                    float g1 = 0.5f * v1 * (1.f + tanhf(t1));
                    __nv_bfloat162 h, l;
                    h.x = __float2bfloat16(g0);
                    l.x = __float2bfloat16(g0 - __bfloat162float(h.x));
                    h.y = __float2bfloat16(g1);
                    l.y = __float2bfloat16(g1 - __bfloat162float(h.y));
                    *(__nv_bfloat162*)&hh[base + ni * 8] = h;
                    *(__nv_bfloat162*)&hl[base + ni * 8] = l;
                }
            } else {
                float w = g_rw[row0 + mloc];
                size_t base = (size_t)(row0 + mloc) * HH + n0 + wn * 32 + (lane & 3) * 2;
#pragma unroll
                for (int ni = 0; ni < 4; ni++) {
                    float2 o;
                    o.x = acc[mi][ni][hr * 2 + 0] * w;
                    o.y = acc[mi][ni][hr * 2 + 1] * w;
                    *(float2*)&outp[base + ni * 8] = o;
                }
            }
        }
    }
}

// ---------------- combine ----------------
__global__ void combine_kernel(float* __restrict__ y) {
    int idx = blockIdx.x * blockDim.x + threadIdx.x;
    int t = idx >> 9, c4 = idx & 511;
    const float4* o = (const float4*)(g_pool + OFF_OUT);
    int p0 = g_pos[t * 2], p1 = g_pos[t * 2 + 1];
    float4 v0 = o[(size_t)p0 * 512 + c4];
    float4 v1 = o[(size_t)p1 * 512 + c4];
    float4 r;
    r.x = v0.x + v1.x; r.y = v0.y + v1.y;
    r.z = v0.z + v1.z; r.w = v0.w + v1.w;
    ((float4*)y)[idx] = r;
}

// ---------------- launch ----------------
extern "C" void kernel_launch(void* const* d_in, const int* in_sizes, int n_in,
                              void* d_out, int out_size) {
    const float* x  = (const float*)d_in[0];
    const float* rw = (const float*)d_in[1];
    const float* w1 = (const float*)d_in[2];
    const float* w2 = (const float*)d_in[3];
    float* y = (float*)d_out;

    cudaFuncSetAttribute(moe_mma_kernel<0>,
                         cudaFuncAttributeMaxDynamicSharedMemorySize, SMEM_DYN);
    cudaFuncSetAttribute(moe_mma_kernel<1>,
                         cudaFuncAttributeMaxDynamicSharedMemorySize, SMEM_DYN);

    init_kernel<<<1, 32>>>();
    router_kernel<<<TT / 8, 256>>>(x, rw);
    build_kernel<<<1, 32>>>(y, (long long)out_size);
    scatter_kernel<<<TK / 256, 256>>>();
    convert_x_kernel<<<(TT * HH / 4) / 256, 256>>>(x);

    moe_mma_kernel<0><<<dim3(II / 128, 136), 256, SMEM_DYN>>>(w1);
    moe_mma_kernel<1><<<dim3(HH / 128, 136), 256, SMEM_DYN>>>(w2);

    combine_kernel<<<(TT * HH / 4) / 256, 256>>>(y);
}

// round 11
// speedup vs baseline: 1.3303x; 1.1769x over previous
#include <cuda_runtime.h>
#include <cuda_bf16.h>
#include <cstdint>

#define TT 8192
#define HH 2048
#define II 4096
#define EE 8
#define TK (TT*2)
#define MAXTILES 144
#define BM 128
#define BK 16

// smem: A 4 stages x 8192 (hi 4096 | lo 4096), pitch 32B
//       B 2 stages x 8704 (hi 4352 | lo 4352), pitch 272B
#define ABASE 0
#define ASTG  8192
#define BBASE 32768
#define BSTG  8704
#define BPITCH 272
#define SMEM_DYN 50176

// ---- pool (402.9MB statics; ~1GB breaks module load — R4/R5 lesson) ----
#define OFF_HH  0ULL
#define OFF_HL  134217728ULL
#define OFF_X   268435456ULL
#define OFF_XL  301989888ULL
#define OFF_OUT 268435456ULL
#define POOL_BYTES 402653184ULL

__device__ char g_pool[POOL_BYTES];
__device__ int   g_topi[TK];
__device__ float g_topw[TK];
__device__ int   g_rowtok[TK];
__device__ float g_rw[TK];
__device__ int   g_pos[TK];
__device__ int   g_counts[EE];
__device__ int   g_offsets[EE + 1];
__device__ int   g_fill[EE];
__device__ int   g_tile_e[MAXTILES];
__device__ int   g_tile_row[MAXTILES];
__device__ int   g_tile_rows[MAXTILES];
__device__ int   g_num_tiles;

// ---------------- PTX helpers (sm_80 baseline ISA) ----------------
__device__ __forceinline__ uint32_t smem_u32(const void* p) {
    uint32_t a;
    asm("{ .reg .u64 t; cvta.to.shared.u64 t, %1; cvt.u32.u64 %0, t; }"
        : "=r"(a) : "l"(p));
    return a;
}
__device__ __forceinline__ void cpasync16(uint32_t dst, const void* src) {
    asm volatile("cp.async.cg.shared.global [%0], [%1], 16;"
                 :: "r"(dst), "l"(src) : "memory");
}
__device__ __forceinline__ void ldmx4(uint32_t* r, uint32_t addr) {
    asm volatile("ldmatrix.sync.aligned.m8n8.x4.shared.b16 {%0,%1,%2,%3}, [%4];"
                 : "=r"(r[0]), "=r"(r[1]), "=r"(r[2]), "=r"(r[3]) : "r"(addr));
}
__device__ __forceinline__ void ldmx4t(uint32_t* r, uint32_t addr) {
    asm volatile("ldmatrix.sync.aligned.m8n8.x4.trans.shared.b16 {%0,%1,%2,%3}, [%4];"
                 : "=r"(r[0]), "=r"(r[1]), "=r"(r[2]), "=r"(r[3]) : "r"(addr));
}
__device__ __forceinline__ void mma16816(float* d, const uint32_t* a,
                                         const uint32_t* b) {
    asm volatile(
        "mma.sync.aligned.m16n8k16.row.col.f32.bf16.bf16.f32 "
        "{%0,%1,%2,%3}, {%4,%5,%6,%7}, {%8,%9}, {%0,%1,%2,%3};"
        : "+f"(d[0]), "+f"(d[1]), "+f"(d[2]), "+f"(d[3])
        : "r"(a[0]), "r"(a[1]), "r"(a[2]), "r"(a[3]), "r"(b[0]), "r"(b[1]));
}

// ---------------- small kernels (proven) ----------------
__global__ void init_kernel() {
    int t = threadIdx.x;
    if (t < EE) { g_counts[t] = 0; g_fill[t] = 0; }
    if (t == 0) g_num_tiles = 0;
}

__global__ void router_kernel(const float* __restrict__ x,
                              const float* __restrict__ rw) {
    int warp = (blockIdx.x * blockDim.x + threadIdx.x) >> 5;
    int lane = threadIdx.x & 31;
    if (warp >= TT) return;
    const float* xr = x + (size_t)warp * HH;
    float acc[EE];
#pragma unroll
    for (int e = 0; e < EE; e++) acc[e] = 0.f;
    for (int i = lane * 4; i < HH; i += 128) {
        float4 xv = *(const float4*)&xr[i];
#pragma unroll
        for (int e = 0; e < EE; e++) {
            float4 wv = *(const float4*)&rw[e * HH + i];
            acc[e] += xv.x * wv.x + xv.y * wv.y + xv.z * wv.z + xv.w * wv.w;
        }
    }
#pragma unroll
    for (int e = 0; e < EE; e++)
#pragma unroll
        for (int off = 16; off; off >>= 1)
            acc[e] += __shfl_xor_sync(0xffffffffu, acc[e], off);
    if (lane == 0) {
        float mx = acc[0];
#pragma unroll
        for (int e = 1; e < EE; e++) mx = fmaxf(mx, acc[e]);
        float p[EE], s = 0.f;
#pragma unroll
        for (int e = 0; e < EE; e++) { p[e] = expf(acc[e] - mx); s += p[e]; }
        float inv = 1.f / s;
        int i1 = 0; float v1 = p[0];
#pragma unroll
        for (int e = 1; e < EE; e++) if (p[e] > v1) { v1 = p[e]; i1 = e; }
        int i2 = -1; float v2 = -1.f;
#pragma unroll
        for (int e = 0; e < EE; e++)
            if (e != i1 && p[e] > v2) { v2 = p[e]; i2 = e; }
        g_topi[warp * 2]     = i1; g_topw[warp * 2]     = v1 * inv;
        g_topi[warp * 2 + 1] = i2; g_topw[warp * 2 + 1] = v2 * inv;
        atomicAdd(&g_counts[i1], 1);
        atomicAdd(&g_counts[i2], 1);
    }
}

__global__ void build_kernel(float* d_out, long long out_size) {
    if (threadIdx.x != 0) return;
    int off = 0;
    for (int e = 0; e < EE; e++) { g_offsets[e] = off; off += g_counts[e]; }
    g_offsets[EE] = off;
    int nt = 0;
    for (int e = 0; e < EE; e++) {
        int n = g_counts[e];
        for (int j = 0; j < n; j += BM) {
            g_tile_e[nt]    = e;
            g_tile_row[nt]  = g_offsets[e] + j;
            g_tile_rows[nt] = (n - j < BM) ? (n - j) : BM;
            nt++;
        }
    }
    g_num_tiles = nt;
    long long base = (long long)TT * HH;
    long long extra = out_size - base;
    for (long long i = 0; i < extra; i++)
        d_out[base + i] = (i < EE) ? (float)g_counts[i] : 0.f;
}

__global__ void scatter_kernel() {
    int i = blockIdx.x * blockDim.x + threadIdx.x;
    if (i >= TK) return;
    int e = g_topi[i];
    int p = g_offsets[e] + atomicAdd(&g_fill[e], 1);
    g_rowtok[p] = i >> 1;
    g_rw[p]     = g_topw[i];
    g_pos[i]    = p;
}

// ---------------- x -> bf16 hi/lo split ----------------
__global__ void convert_x_kernel(const float* __restrict__ x) {
    int i = blockIdx.x * blockDim.x + threadIdx.x;
    float4 v = ((const float4*)x)[i];
    __nv_bfloat162 h0, h1, l0, l1;
    h0.x = __float2bfloat16(v.x); l0.x = __float2bfloat16(v.x - __bfloat162float(h0.x));
    h0.y = __float2bfloat16(v.y); l0.y = __float2bfloat16(v.y - __bfloat162float(h0.y));
    h1.x = __float2bfloat16(v.z); l1.x = __float2bfloat16(v.z - __bfloat162float(h1.x));
    h1.y = __float2bfloat16(v.w); l1.y = __float2bfloat16(v.w - __bfloat162float(h1.y));
    __nv_bfloat162* oh = (__nv_bfloat162*)(g_pool + OFF_X);
    __nv_bfloat162* ol = (__nv_bfloat162*)(g_pool + OFF_XL);
    oh[i * 2] = h0; oh[i * 2 + 1] = h1;
    ol[i * 2] = l0; ol[i * 2 + 1] = l1;
}

// ---------------- grouped GEMM: 128x128, BK=16, 4-stage A, 1 sync/chunk ----
// MODE 0: h = gelu(xs @ w1)   MODE 1: out = rw*(h @ w2)
// Warp grid 2(m) x 4(n), warp tile 64x32 (R7-proven fragment mapping).
template <int MODE>
__global__ __launch_bounds__(256, 2) void moe_mma_kernel(const float* __restrict__ W) {
    const int KLEN = MODE ? II : HH;
    const int BROW = MODE ? HH : II;
    const int NC = KLEN / BK;
    int tile = blockIdx.y;
    if (tile >= g_num_tiles) return;
    const int e = g_tile_e[tile], row0 = g_tile_row[tile], rows = g_tile_rows[tile];
    const int n0 = blockIdx.x * 128;
    const int tid = threadIdx.x, wid = tid >> 5, lane = tid & 31;
    const int wm = wid & 1, wn = wid >> 1;   // 64(m) x 32(n) warp tile

    extern __shared__ __align__(128) char dsm[];
    uint32_t sb = smem_u32(dsm);

    const __nv_bfloat16* Ahg = (const __nv_bfloat16*)(g_pool + (MODE ? OFF_HH : OFF_X));
    const __nv_bfloat16* Alg = (const __nv_bfloat16*)(g_pool + (MODE ? OFF_HL : OFF_XL));
    const float* We = W + (size_t)e * KLEN * BROW;

    // A: thread pair per row (R10-proven addressing)
    const int arow_i = tid >> 1, ahalf = tid & 1;
    const int arow = (arow_i < rows) ? arow_i : (rows - 1);
    const size_t abase = MODE ? (size_t)(row0 + arow) * II
                              : (size_t)g_rowtok[row0 + arow] * HH;
    auto load_A = [&](int st, int k0) {
        uint32_t so = sb + (uint32_t)(st * ASTG + arow_i * 32 + ahalf * 16);
        cpasync16(so,        (const char*)(Ahg + abase + k0) + ahalf * 16);
        cpasync16(so + 4096, (const char*)(Alg + abase + k0) + ahalf * 16);
        asm volatile("cp.async.commit_group;" ::: "memory");
    };

    // B: thread owns row k=tid>>4 (0..15), 8 floats at col (tid&15)*8
    const int bk_r = tid >> 4, bn_r = (tid & 15) * 8;
    const float* Bsrc = We + (size_t)bk_r * BROW + n0 + bn_r;
    float4 br0, br1;
    auto ldg_B = [&](int k0) {
        const float4* p = (const float4*)(Bsrc + (size_t)k0 * BROW);
        br0 = p[0]; br1 = p[1];
    };
    auto sts_B = [&](int st) {
        float vs[8] = {br0.x, br0.y, br0.z, br0.w, br1.x, br1.y, br1.z, br1.w};
        __align__(16) __nv_bfloat16 hb[8], lb[8];
#pragma unroll
        for (int i = 0; i < 8; i++) {
            hb[i] = __float2bfloat16(vs[i]);
            lb[i] = __float2bfloat16(vs[i] - __bfloat162float(hb[i]));
        }
        char* bb = dsm + BBASE + st * BSTG + bk_r * BPITCH + bn_r * 2;
        *(uint4*)bb          = *(uint4*)hb;
        *(uint4*)(bb + 4352) = *(uint4*)lb;
    };

    float acc[4][4][4];
#pragma unroll
    for (int a = 0; a < 4; a++)
#pragma unroll
        for (int b = 0; b < 4; b++)
#pragma unroll
            for (int c = 0; c < 4; c++) acc[a][b][c] = 0.f;

    // prologue: A(0..2) in flight; B(0) -> smem; B(1) in regs
    ldg_B(0);
    load_A(0, 0);
    if (NC > 1) load_A(1, BK);
    if (NC > 2) load_A(2, 2 * BK);
    sts_B(0);
    if (NC > 1) ldg_B(BK);
    asm volatile("cp.async.wait_group 2;" ::: "memory");
    __syncthreads();

    for (int ch = 0; ch < NC; ch++) {
        const int stA = ch & 3, stB = ch & 1;
        // issue next-stage fills first so they overlap the MMAs below
        if (ch + 1 < NC) sts_B(stB ^ 1);            // B(ch+1) regs -> smem
        if (ch + 2 < NC) ldg_B((ch + 2) * BK);      // prefetch B(ch+2)
        if (ch + 3 < NC) load_A((ch + 3) & 3, (ch + 3) * BK);

        uint32_t Ast = sb + (uint32_t)(stA * ASTG);
        uint32_t Bst = sb + (uint32_t)(BBASE + stB * BSTG);
        uint32_t Afh[4][4], Afl[4][4], Bfh[8], Bfl[8];
#pragma unroll
        for (int mi = 0; mi < 4; mi++) {
            uint32_t ad = Ast + (uint32_t)(
                (wm * 64 + mi * 16 + (lane & 15)) * 32 + ((lane >> 4) & 1) * 16);
            ldmx4(Afh[mi], ad);
            ldmx4(Afl[mi], ad + 4096);
        }
#pragma unroll
        for (int np = 0; np < 2; np++) {
            int krow = ((lane >> 3) & 1) * 8 + (lane & 7);
            int ncol = wn * 32 + np * 16 + ((lane >> 4) & 1) * 8;
            uint32_t bd = Bst + (uint32_t)(krow * BPITCH + ncol * 2);
            ldmx4t(&Bfh[np * 4], bd);
            ldmx4t(&Bfl[np * 4], bd + 4352);
        }
#pragma unroll
        for (int mi = 0; mi < 4; mi++)
#pragma unroll
            for (int ni = 0; ni < 4; ni++) {
                mma16816(acc[mi][ni], Afh[mi], &Bfh[ni * 2]);
                mma16816(acc[mi][ni], Afl[mi], &Bfh[ni * 2]);
                mma16816(acc[mi][ni], Afh[mi], &Bfl[ni * 2]);
            }

        // A(ch+1) must be resident for next iter (keep 2 newest in flight)
        if (ch + 1 < NC) asm volatile("cp.async.wait_group 2;" ::: "memory");
        __syncthreads();
    }

    // ---------------- epilogue (R7-proven) ----------------
    __nv_bfloat16* hh = (__nv_bfloat16*)(g_pool + OFF_HH);
    __nv_bfloat16* hl = (__nv_bfloat16*)(g_pool + OFF_HL);
    float* outp = (float*)(g_pool + OFF_OUT);
#pragma unroll
    for (int mi = 0; mi < 4; mi++) {
#pragma unroll
        for (int hr = 0; hr < 2; hr++) {
            int mloc = wm * 64 + mi * 16 + hr * 8 + (lane >> 2);
            if (mloc >= rows) continue;
            if (MODE == 0) {
                size_t base = (size_t)(row0 + mloc) * II + n0 + wn * 32 + (lane & 3) * 2;
#pragma unroll
                for (int ni = 0; ni < 4; ni++) {
                    float v0 = acc[mi][ni][hr * 2 + 0];
                    float v1 = acc[mi][ni][hr * 2 + 1];
                    float t0 = 0.7978845608028654f * (v0 + 0.044715f * v0 * v0 * v0);
                    float t1 = 0.7978845608028654f * (v1 + 0.044715f * v1 * v1 * v1);
                    float g0 = 0.5f * v0 * (1.f + tanhf(t0));
                    float g1 = 0.5f * v1 * (1.f + tanhf(t1));
                    __nv_bfloat162 h, l;
                    h.x = __float2bfloat16(g0);
                    l.x = __float2bfloat16(g0 - __bfloat162float(h.x));
                    h.y = __float2bfloat16(g1);
                    l.y = __float2bfloat16(g1 - __bfloat162float(h.y));
                    *(__nv_bfloat162*)&hh[base + ni * 8] = h;
                    *(__nv_bfloat162*)&hl[base + ni * 8] = l;
                }
            } else {
                float w = g_rw[row0 + mloc];
                size_t base = (size_t)(row0 + mloc) * HH + n0 + wn * 32 + (lane & 3) * 2;
#pragma unroll
                for (int ni = 0; ni < 4; ni++) {
                    float2 o;
                    o.x = acc[mi][ni][hr * 2 + 0] * w;
                    o.y = acc[mi][ni][hr * 2 + 1] * w;
                    *(float2*)&outp[base + ni * 8] = o;
                }
            }
        }
    }
}

// ---------------- combine ----------------
__global__ void combine_kernel(float* __restrict__ y) {
    int idx = blockIdx.x * blockDim.x + threadIdx.x;
    int t = idx >> 9, c4 = idx & 511;
    const float4* o = (const float4*)(g_pool + OFF_OUT);
    int p0 = g_pos[t * 2], p1 = g_pos[t * 2 + 1];
    float4 v0 = o[(size_t)p0 * 512 + c4];
    float4 v1 = o[(size_t)p1 * 512 + c4];
    float4 r;
    r.x = v0.x + v1.x; r.y = v0.y + v1.y;
    r.z = v0.z + v1.z; r.w = v0.w + v1.w;
    ((float4*)y)[idx] = r;
}

// ---------------- launch ----------------
extern "C" void kernel_launch(void* const* d_in, const int* in_sizes, int n_in,
                              void* d_out, int out_size) {
    const float* x  = (const float*)d_in[0];
    const float* rw = (const float*)d_in[1];
    const float* w1 = (const float*)d_in[2];
    const float* w2 = (const float*)d_in[3];
    float* y = (float*)d_out;

    cudaFuncSetAttribute(moe_mma_kernel<0>,
                         cudaFuncAttributeMaxDynamicSharedMemorySize, SMEM_DYN);
    cudaFuncSetAttribute(moe_mma_kernel<1>,
                         cudaFuncAttributeMaxDynamicSharedMemorySize, SMEM_DYN);

    init_kernel<<<1, 32>>>();
    router_kernel<<<TT / 8, 256>>>(x, rw);
    build_kernel<<<1, 32>>>(y, (long long)out_size);
    scatter_kernel<<<TK / 256, 256>>>();
    convert_x_kernel<<<(TT * HH / 4) / 256, 256>>>(x);

    moe_mma_kernel<0><<<dim3(II / 128, 136), 256, SMEM_DYN>>>(w1);
    moe_mma_kernel<1><<<dim3(HH / 128, 136), 256, SMEM_DYN>>>(w2);

    combine_kernel<<<(TT * HH / 4) / 256, 256>>>(y);
}

// round 12
// speedup vs baseline: 1.6781x; 1.2614x over previous
#include <cuda_runtime.h>
#include <cuda_fp16.h>
#include <cstdint>

#define TT 8192
#define HH 2048
#define II 4096
#define EE 8
#define TK (TT*2)
#define MAXTILES 144
#define BM 128
#define BK 16

// smem: A 4 stages x 8192 (hi 4096 | lo 4096), pitch 32B
//       B 2 stages x 4352 (hi only), pitch 272B
#define ASTG  8192
#define BBASE 32768
#define BSTG  4352
#define BPITCH 272
#define SMEM_DYN 41472

// ---- pool (402.9MB statics; ~1GB breaks module load — R4/R5 lesson) ----
#define OFF_HH  0ULL                 // h hi fp16 [TK][II] 134MB
#define OFF_HL  134217728ULL         // h lo fp16 [TK][II] 134MB
#define OFF_X   268435456ULL         // x hi fp16 [TT][HH]  32MB (dead after GEMM1)
#define OFF_XL  301989888ULL         // x lo fp16 [TT][HH]  32MB
#define OFF_OUT 268435456ULL         // out fp32 [TK][HH] 134MB (reuses x region)
#define POOL_BYTES 402653184ULL

__device__ char g_pool[POOL_BYTES];
__device__ int   g_topi[TK];
__device__ float g_topw[TK];
__device__ int   g_rowtok[TK];
__device__ float g_rw[TK];
__device__ int   g_pos[TK];
__device__ int   g_counts[EE];
__device__ int   g_offsets[EE + 1];
__device__ int   g_fill[EE];
__device__ int   g_tile_e[MAXTILES];
__device__ int   g_tile_row[MAXTILES];
__device__ int   g_tile_rows[MAXTILES];
__device__ int   g_num_tiles;

// ---------------- PTX helpers (sm_80 baseline ISA) ----------------
__device__ __forceinline__ uint32_t smem_u32(const void* p) {
    uint32_t a;
    asm("{ .reg .u64 t; cvta.to.shared.u64 t, %1; cvt.u32.u64 %0, t; }"
        : "=r"(a) : "l"(p));
    return a;
}
__device__ __forceinline__ void cpasync16(uint32_t dst, const void* src) {
    asm volatile("cp.async.cg.shared.global [%0], [%1], 16;"
                 :: "r"(dst), "l"(src) : "memory");
}
__device__ __forceinline__ void ldmx4(uint32_t* r, uint32_t addr) {
    asm volatile("ldmatrix.sync.aligned.m8n8.x4.shared.b16 {%0,%1,%2,%3}, [%4];"
                 : "=r"(r[0]), "=r"(r[1]), "=r"(r[2]), "=r"(r[3]) : "r"(addr));
}
__device__ __forceinline__ void ldmx4t(uint32_t* r, uint32_t addr) {
    asm volatile("ldmatrix.sync.aligned.m8n8.x4.trans.shared.b16 {%0,%1,%2,%3}, [%4];"
                 : "=r"(r[0]), "=r"(r[1]), "=r"(r[2]), "=r"(r[3]) : "r"(addr));
}
__device__ __forceinline__ void mma16816(float* d, const uint32_t* a,
                                         const uint32_t* b) {
    asm volatile(
        "mma.sync.aligned.m16n8k16.row.col.f32.f16.f16.f32 "
        "{%0,%1,%2,%3}, {%4,%5,%6,%7}, {%8,%9}, {%0,%1,%2,%3};"
        : "+f"(d[0]), "+f"(d[1]), "+f"(d[2]), "+f"(d[3])
        : "r"(a[0]), "r"(a[1]), "r"(a[2]), "r"(a[3]), "r"(b[0]), "r"(b[1]));
}

// ---------------- x -> fp16 hi/lo split (+ counter init in block 0) --------
__global__ void convert_x_kernel(const float* __restrict__ x) {
    if (blockIdx.x == 0 && threadIdx.x < 32) {
        int t = threadIdx.x;
        if (t < EE) { g_counts[t] = 0; g_fill[t] = 0; }
        if (t == 0) g_num_tiles = 0;
    }
    int i = blockIdx.x * blockDim.x + threadIdx.x;
    float4 v = ((const float4*)x)[i];
    __half2 h0, h1, l0, l1;
    h0.x = __float2half_rn(v.x); l0.x = __float2half_rn(v.x - __half2float(h0.x));
    h0.y = __float2half_rn(v.y); l0.y = __float2half_rn(v.y - __half2float(h0.y));
    h1.x = __float2half_rn(v.z); l1.x = __float2half_rn(v.z - __half2float(h1.x));
    h1.y = __float2half_rn(v.w); l1.y = __float2half_rn(v.w - __half2float(h1.y));
    __half2* oh = (__half2*)(g_pool + OFF_X);
    __half2* ol = (__half2*)(g_pool + OFF_XL);
    oh[i * 2] = h0; oh[i * 2 + 1] = h1;
    ol[i * 2] = l0; ol[i * 2 + 1] = l1;
}

// ---------------- router (proven) ----------------
__global__ void router_kernel(const float* __restrict__ x,
                              const float* __restrict__ rw) {
    int warp = (blockIdx.x * blockDim.x + threadIdx.x) >> 5;
    int lane = threadIdx.x & 31;
    if (warp >= TT) return;
    const float* xr = x + (size_t)warp * HH;
    float acc[EE];
#pragma unroll
    for (int e = 0; e < EE; e++) acc[e] = 0.f;
    for (int i = lane * 4; i < HH; i += 128) {
        float4 xv = *(const float4*)&xr[i];
#pragma unroll
        for (int e = 0; e < EE; e++) {
            float4 wv = *(const float4*)&rw[e * HH + i];
            acc[e] += xv.x * wv.x + xv.y * wv.y + xv.z * wv.z + xv.w * wv.w;
        }
    }
#pragma unroll
    for (int e = 0; e < EE; e++)
#pragma unroll
        for (int off = 16; off; off >>= 1)
            acc[e] += __shfl_xor_sync(0xffffffffu, acc[e], off);
    if (lane == 0) {
        float mx = acc[0];
#pragma unroll
        for (int e = 1; e < EE; e++) mx = fmaxf(mx, acc[e]);
        float p[EE], s = 0.f;
#pragma unroll
        for (int e = 0; e < EE; e++) { p[e] = expf(acc[e] - mx); s += p[e]; }
        float inv = 1.f / s;
        int i1 = 0; float v1 = p[0];
#pragma unroll
        for (int e = 1; e < EE; e++) if (p[e] > v1) { v1 = p[e]; i1 = e; }
        int i2 = -1; float v2 = -1.f;
#pragma unroll
        for (int e = 0; e < EE; e++)
            if (e != i1 && p[e] > v2) { v2 = p[e]; i2 = e; }
        g_topi[warp * 2]     = i1; g_topw[warp * 2]     = v1 * inv;
        g_topi[warp * 2 + 1] = i2; g_topw[warp * 2 + 1] = v2 * inv;
        atomicAdd(&g_counts[i1], 1);
        atomicAdd(&g_counts[i2], 1);
    }
}

// ---------------- build offsets + tiles, then scatter (merged) -------------
__global__ void build_scatter_kernel(float* d_out, long long out_size) {
    int tid = threadIdx.x;
    if (tid == 0) {
        int off = 0;
        for (int e = 0; e < EE; e++) { g_offsets[e] = off; off += g_counts[e]; }
        g_offsets[EE] = off;
        int nt = 0;
        for (int e = 0; e < EE; e++) {
            int n = g_counts[e];
            for (int j = 0; j < n; j += BM) {
                g_tile_e[nt]    = e;
                g_tile_row[nt]  = g_offsets[e] + j;
                g_tile_rows[nt] = (n - j < BM) ? (n - j) : BM;
                nt++;
            }
        }
        g_num_tiles = nt;
        long long base = (long long)TT * HH;
        long long extra = out_size - base;
        for (long long i = 0; i < extra; i++)
            d_out[base + i] = (i < EE) ? (float)g_counts[i] : 0.f;
    }
    __syncthreads();
    for (int i = tid; i < TK; i += blockDim.x) {
        int e = g_topi[i];
        int p = g_offsets[e] + atomicAdd(&g_fill[e], 1);
        g_rowtok[p] = i >> 1;
        g_rw[p]     = g_topw[i];
        g_pos[i]    = p;
    }
}

// ---------------- grouped GEMM: fp16 split-A 2-term, R11 pipeline ----------
// MODE 0: h = gelu(xs @ w1)   MODE 1: out = rw*(h @ w2)
// Warp grid 2(m) x 4(n), warp tile 64x32 (R7-proven fragment mapping).
template <int MODE>
__global__ __launch_bounds__(256, 2) void moe_mma_kernel(const float* __restrict__ W) {
    const int KLEN = MODE ? II : HH;
    const int BROW = MODE ? HH : II;
    const int NC = KLEN / BK;
    int tile = blockIdx.y;
    if (tile >= g_num_tiles) return;
    const int e = g_tile_e[tile], row0 = g_tile_row[tile], rows = g_tile_rows[tile];
    const int n0 = blockIdx.x * 128;
    const int tid = threadIdx.x, wid = tid >> 5, lane = tid & 31;
    const int wm = wid & 1, wn = wid >> 1;   // 64(m) x 32(n) warp tile

    extern __shared__ __align__(128) char dsm[];
    uint32_t sb = smem_u32(dsm);

    const __half* Ahg = (const __half*)(g_pool + (MODE ? OFF_HH : OFF_X));
    const __half* Alg = (const __half*)(g_pool + (MODE ? OFF_HL : OFF_XL));
    const float* We = W + (size_t)e * KLEN * BROW;

    // A: thread pair per row
    const int arow_i = tid >> 1, ahalf = tid & 1;
    const int arow = (arow_i < rows) ? arow_i : (rows - 1);
    const size_t abase = MODE ? (size_t)(row0 + arow) * II
                              : (size_t)g_rowtok[row0 + arow] * HH;
    auto load_A = [&](int st, int k0) {
        uint32_t so = sb + (uint32_t)(st * ASTG + arow_i * 32 + ahalf * 16);
        cpasync16(so,        (const char*)(Ahg + abase + k0) + ahalf * 16);
        cpasync16(so + 4096, (const char*)(Alg + abase + k0) + ahalf * 16);
        asm volatile("cp.async.commit_group;" ::: "memory");
    };

    // B: thread owns row k=tid>>4 (0..15), 8 floats at col (tid&15)*8
    const int bk_r = tid >> 4, bn_r = (tid & 15) * 8;
    const float* Bsrc = We + (size_t)bk_r * BROW + n0 + bn_r;
    float4 br0, br1;
    auto ldg_B = [&](int k0) {
        const float4* p = (const float4*)(Bsrc + (size_t)k0 * BROW);
        br0 = p[0]; br1 = p[1];
    };
    auto sts_B = [&](int st) {
        float vs[8] = {br0.x, br0.y, br0.z, br0.w, br1.x, br1.y, br1.z, br1.w};
        __align__(16) __half hb[8];
#pragma unroll
        for (int i = 0; i < 8; i++) hb[i] = __float2half_rn(vs[i]);
        *(uint4*)(dsm + BBASE + st * BSTG + bk_r * BPITCH + bn_r * 2) = *(uint4*)hb;
    };

    float acc[4][4][4];
#pragma unroll
    for (int a = 0; a < 4; a++)
#pragma unroll
        for (int b = 0; b < 4; b++)
#pragma unroll
            for (int c = 0; c < 4; c++) acc[a][b][c] = 0.f;

    // prologue: A(0..2) in flight; B(0) -> smem; B(1) in regs
    ldg_B(0);
    load_A(0, 0);
    load_A(1, BK);
    load_A(2, 2 * BK);
    sts_B(0);
    ldg_B(BK);
    asm volatile("cp.async.wait_group 2;" ::: "memory");
    __syncthreads();

    for (int ch = 0; ch < NC; ch++) {
        const int stA = ch & 3, stB = ch & 1;
        if (ch + 1 < NC) sts_B(stB ^ 1);            // B(ch+1) regs -> smem
        if (ch + 2 < NC) ldg_B((ch + 2) * BK);      // prefetch B(ch+2)
        if (ch + 3 < NC) load_A((ch + 3) & 3, (ch + 3) * BK);

        uint32_t Ast = sb + (uint32_t)(stA * ASTG);
        uint32_t Bst = sb + (uint32_t)(BBASE + stB * BSTG);
        uint32_t Afh[4][4], Afl[4][4], Bfh[8];
#pragma unroll
        for (int mi = 0; mi < 4; mi++) {
            uint32_t ad = Ast + (uint32_t)(
                (wm * 64 + mi * 16 + (lane & 15)) * 32 + ((lane >> 4) & 1) * 16);
            ldmx4(Afh[mi], ad);
            ldmx4(Afl[mi], ad + 4096);
        }
#pragma unroll
        for (int np = 0; np < 2; np++) {
            int krow = ((lane >> 3) & 1) * 8 + (lane & 7);
            int ncol = wn * 32 + np * 16 + ((lane >> 4) & 1) * 8;
            uint32_t bd = Bst + (uint32_t)(krow * BPITCH + ncol * 2);
            ldmx4t(&Bfh[np * 4], bd);
        }
#pragma unroll
        for (int mi = 0; mi < 4; mi++)
#pragma unroll
            for (int ni = 0; ni < 4; ni++) {
                mma16816(acc[mi][ni], Afh[mi], &Bfh[ni * 2]);
                mma16816(acc[mi][ni], Afl[mi], &Bfh[ni * 2]);
            }

        if (ch + 1 < NC) asm volatile("cp.async.wait_group 2;" ::: "memory");
        __syncthreads();
    }

    // ---------------- epilogue ----------------
    __half* hh = (__half*)(g_pool + OFF_HH);
    __half* hl = (__half*)(g_pool + OFF_HL);
    float* outp = (float*)(g_pool + OFF_OUT);
#pragma unroll
    for (int mi = 0; mi < 4; mi++) {
#pragma unroll
        for (int hr = 0; hr < 2; hr++) {
            int mloc = wm * 64 + mi * 16 + hr * 8 + (lane >> 2);
            if (mloc >= rows) continue;
            if (MODE == 0) {
                size_t base = (size_t)(row0 + mloc) * II + n0 + wn * 32 + (lane & 3) * 2;
#pragma unroll
                for (int ni = 0; ni < 4; ni++) {
                    float v0 = acc[mi][ni][hr * 2 + 0];
                    float v1 = acc[mi][ni][hr * 2 + 1];
                    float t0 = 0.7978845608028654f * (v0 + 0.044715f * v0 * v0 * v0);
                    float t1 = 0.7978845608028654f * (v1 + 0.044715f * v1 * v1 * v1);
                    float g0 = 0.5f * v0 * (1.f + tanhf(t0));
                    float g1 = 0.5f * v1 * (1.f + tanhf(t1));
                    __half2 h, l;
                    h.x = __float2half_rn(g0);
                    l.x = __float2half_rn(g0 - __half2float(h.x));
                    h.y = __float2half_rn(g1);
                    l.y = __float2half_rn(g1 - __half2float(h.y));
                    *(__half2*)&hh[base + ni * 8] = h;
                    *(__half2*)&hl[base + ni * 8] = l;
                }
            } else {
                float w = g_rw[row0 + mloc];
                size_t base = (size_t)(row0 + mloc) * HH + n0 + wn * 32 + (lane & 3) * 2;
#pragma unroll
                for (int ni = 0; ni < 4; ni++) {
                    float2 o;
                    o.x = acc[mi][ni][hr * 2 + 0] * w;
                    o.y = acc[mi][ni][hr * 2 + 1] * w;
                    *(float2*)&outp[base + ni * 8] = o;
                }
            }
        }
    }
}

// ---------------- combine ----------------
__global__ void combine_kernel(float* __restrict__ y) {
    int idx = blockIdx.x * blockDim.x + threadIdx.x;
    int t = idx >> 9, c4 = idx & 511;
    const float4* o = (const float4*)(g_pool + OFF_OUT);
    int p0 = g_pos[t * 2], p1 = g_pos[t * 2 + 1];
    float4 v0 = o[(size_t)p0 * 512 + c4];
    float4 v1 = o[(size_t)p1 * 512 + c4];
    float4 r;
    r.x = v0.x + v1.x; r.y = v0.y + v1.y;
    r.z = v0.z + v1.z; r.w = v0.w + v1.w;
    ((float4*)y)[idx] = r;
}

// ---------------- launch ----------------
extern "C" void kernel_launch(void* const* d_in, const int* in_sizes, int n_in,
                              void* d_out, int out_size) {
    const float* x  = (const float*)d_in[0];
    const float* rw = (const float*)d_in[1];
    const float* w1 = (const float*)d_in[2];
    const float* w2 = (const float*)d_in[3];
    float* y = (float*)d_out;

    cudaFuncSetAttribute(moe_mma_kernel<0>,
                         cudaFuncAttributeMaxDynamicSharedMemorySize, SMEM_DYN);
    cudaFuncSetAttribute(moe_mma_kernel<1>,
                         cudaFuncAttributeMaxDynamicSharedMemorySize, SMEM_DYN);

    convert_x_kernel<<<(TT * HH / 4) / 256, 256>>>(x);        // 1 (also inits)
    router_kernel<<<TT / 8, 256>>>(x, rw);                    // 2
    build_scatter_kernel<<<1, 256>>>(y, (long long)out_size); // 3
    moe_mma_kernel<0><<<dim3(II / 128, 136), 256, SMEM_DYN>>>(w1);  // 4 <- ncu slot
    moe_mma_kernel<1><<<dim3(HH / 128, 136), 256, SMEM_DYN>>>(w2);  // 5
    combine_kernel<<<(TT * HH / 4) / 256, 256>>>(y);          // 6
}

// round 13
// speedup vs baseline: 2.5898x; 1.5433x over previous
#include <cuda_runtime.h>
#include <cuda_fp16.h>
#include <cstdint>

#define TT 8192
#define HH 2048
#define II 4096
#define EE 8
#define TK (TT*2)
#define MAXTILES 144
#define BM 128
#define BK 16

// smem: A 4 stages x 4096 (fp16, pitch 32B)
//       B 2 stages x 4352 (fp16, pitch 272B)
#define ASTG  4096
#define BBASE 16384
#define BSTG  4352
#define BPITCH 272
#define SMEM_DYN 25088

// ---- pool (402.9MB statics; ~1GB breaks module load — R4/R5 lesson) ----
#define OFF_HH  0ULL                 // h fp16 [TK][II] 134MB
#define OFF_X   268435456ULL         // x fp16 [TT][HH]  32MB (dead after GEMM1)
#define OFF_OUT 134217728ULL         // out fp32 [TK][HH] 134MB
#define POOL_BYTES 402653184ULL

__device__ char g_pool[POOL_BYTES];
__device__ int   g_topi[TK];
__device__ float g_topw[TK];
__device__ int   g_rowtok[TK];
__device__ float g_rw[TK];
__device__ int   g_pos[TK];
__device__ int   g_counts[EE];
__device__ int   g_offsets[EE + 1];
__device__ int   g_fill[EE];
__device__ int   g_tile_e[MAXTILES];
__device__ int   g_tile_row[MAXTILES];
__device__ int   g_tile_rows[MAXTILES];
__device__ int   g_num_tiles;

// ---------------- PTX helpers (sm_80 baseline ISA) ----------------
__device__ __forceinline__ uint32_t smem_u32(const void* p) {
    uint32_t a;
    asm("{ .reg .u64 t; cvta.to.shared.u64 t, %1; cvt.u32.u64 %0, t; }"
        : "=r"(a) : "l"(p));
    return a;
}
__device__ __forceinline__ void cpasync16(uint32_t dst, const void* src) {
    asm volatile("cp.async.cg.shared.global [%0], [%1], 16;"
                 :: "r"(dst), "l"(src) : "memory");
}
__device__ __forceinline__ void ldmx4(uint32_t* r, uint32_t addr) {
    asm volatile("ldmatrix.sync.aligned.m8n8.x4.shared.b16 {%0,%1,%2,%3}, [%4];"
                 : "=r"(r[0]), "=r"(r[1]), "=r"(r[2]), "=r"(r[3]) : "r"(addr));
}
__device__ __forceinline__ void ldmx4t(uint32_t* r, uint32_t addr) {
    asm volatile("ldmatrix.sync.aligned.m8n8.x4.trans.shared.b16 {%0,%1,%2,%3}, [%4];"
                 : "=r"(r[0]), "=r"(r[1]), "=r"(r[2]), "=r"(r[3]) : "r"(addr));
}
__device__ __forceinline__ void mma16816(float* d, const uint32_t* a,
                                         const uint32_t* b) {
    asm volatile(
        "mma.sync.aligned.m16n8k16.row.col.f32.f16.f16.f32 "
        "{%0,%1,%2,%3}, {%4,%5,%6,%7}, {%8,%9}, {%0,%1,%2,%3};"
        : "+f"(d[0]), "+f"(d[1]), "+f"(d[2]), "+f"(d[3])
        : "r"(a[0]), "r"(a[1]), "r"(a[2]), "r"(a[3]), "r"(b[0]), "r"(b[1]));
}

// ---------------- x -> fp16 (+ counter init in block 0) --------------------
__global__ void convert_x_kernel(const float* __restrict__ x) {
    if (blockIdx.x == 0 && threadIdx.x < 32) {
        int t = threadIdx.x;
        if (t < EE) { g_counts[t] = 0; g_fill[t] = 0; }
        if (t == 0) g_num_tiles = 0;
    }
    int i = blockIdx.x * blockDim.x + threadIdx.x;
    float4 v = ((const float4*)x)[i];
    __half2 h0, h1;
    h0.x = __float2half_rn(v.x); h0.y = __float2half_rn(v.y);
    h1.x = __float2half_rn(v.z); h1.y = __float2half_rn(v.w);
    __half2* oh = (__half2*)(g_pool + OFF_X);
    oh[i * 2] = h0; oh[i * 2 + 1] = h1;
}

// ---------------- router (proven) ----------------
__global__ void router_kernel(const float* __restrict__ x,
                              const float* __restrict__ rw) {
    int warp = (blockIdx.x * blockDim.x + threadIdx.x) >> 5;
    int lane = threadIdx.x & 31;
    if (warp >= TT) return;
    const float* xr = x + (size_t)warp * HH;
    float acc[EE];
#pragma unroll
    for (int e = 0; e < EE; e++) acc[e] = 0.f;
    for (int i = lane * 4; i < HH; i += 128) {
        float4 xv = *(const float4*)&xr[i];
#pragma unroll
        for (int e = 0; e < EE; e++) {
            float4 wv = *(const float4*)&rw[e * HH + i];
            acc[e] += xv.x * wv.x + xv.y * wv.y + xv.z * wv.z + xv.w * wv.w;
        }
    }
#pragma unroll
    for (int e = 0; e < EE; e++)
#pragma unroll
        for (int off = 16; off; off >>= 1)
            acc[e] += __shfl_xor_sync(0xffffffffu, acc[e], off);
    if (lane == 0) {
        float mx = acc[0];
#pragma unroll
        for (int e = 1; e < EE; e++) mx = fmaxf(mx, acc[e]);
        float p[EE], s = 0.f;
#pragma unroll
        for (int e = 0; e < EE; e++) { p[e] = expf(acc[e] - mx); s += p[e]; }
        float inv = 1.f / s;
        int i1 = 0; float v1 = p[0];
#pragma unroll
        for (int e = 1; e < EE; e++) if (p[e] > v1) { v1 = p[e]; i1 = e; }
        int i2 = -1; float v2 = -1.f;
#pragma unroll
        for (int e = 0; e < EE; e++)
            if (e != i1 && p[e] > v2) { v2 = p[e]; i2 = e; }
        g_topi[warp * 2]     = i1; g_topw[warp * 2]     = v1 * inv;
        g_topi[warp * 2 + 1] = i2; g_topw[warp * 2 + 1] = v2 * inv;
        atomicAdd(&g_counts[i1], 1);
        atomicAdd(&g_counts[i2], 1);
    }
}

// ---------------- build offsets + tiles, then scatter (merged) -------------
__global__ void build_scatter_kernel(float* d_out, long long out_size) {
    int tid = threadIdx.x;
    if (tid == 0) {
        int off = 0;
        for (int e = 0; e < EE; e++) { g_offsets[e] = off; off += g_counts[e]; }
        g_offsets[EE] = off;
        int nt = 0;
        for (int e = 0; e < EE; e++) {
            int n = g_counts[e];
            for (int j = 0; j < n; j += BM) {
                g_tile_e[nt]    = e;
                g_tile_row[nt]  = g_offsets[e] + j;
                g_tile_rows[nt] = (n - j < BM) ? (n - j) : BM;
                nt++;
            }
        }
        g_num_tiles = nt;
        long long base = (long long)TT * HH;
        long long extra = out_size - base;
        for (long long i = 0; i < extra; i++)
            d_out[base + i] = (i < EE) ? (float)g_counts[i] : 0.f;
    }
    __syncthreads();
    for (int i = tid; i < TK; i += blockDim.x) {
        int e = g_topi[i];
        int p = g_offsets[e] + atomicAdd(&g_fill[e], 1);
        g_rowtok[p] = i >> 1;
        g_rw[p]     = g_topw[i];
        g_pos[i]    = p;
    }
}

// ---------------- grouped GEMM: pure fp16 single-term, R11 pipeline --------
// MODE 0: h = gelu(xs @ w1)   MODE 1: out = rw*(h @ w2)
// Warp grid 2(m) x 4(n), warp tile 64x32 (R7-proven fragment mapping).
template <int MODE>
__global__ __launch_bounds__(256, 2) void moe_mma_kernel(const float* __restrict__ W) {
    const int KLEN = MODE ? II : HH;
    const int BROW = MODE ? HH : II;
    const int NC = KLEN / BK;
    int tile = blockIdx.y;
    if (tile >= g_num_tiles) return;
    const int e = g_tile_e[tile], row0 = g_tile_row[tile], rows = g_tile_rows[tile];
    const int n0 = blockIdx.x * 128;
    const int tid = threadIdx.x, wid = tid >> 5, lane = tid & 31;
    const int wm = wid & 1, wn = wid >> 1;   // 64(m) x 32(n) warp tile

    extern __shared__ __align__(128) char dsm[];
    uint32_t sb = smem_u32(dsm);

    const __half* Ahg = (const __half*)(g_pool + (MODE ? OFF_HH : OFF_X));
    const float* We = W + (size_t)e * KLEN * BROW;

    // A: thread pair per row (16 fp16 = 32B per row; each thread 16B)
    const int arow_i = tid >> 1, ahalf = tid & 1;
    const int arow = (arow_i < rows) ? arow_i : (rows - 1);
    const size_t abase = MODE ? (size_t)(row0 + arow) * II
                              : (size_t)g_rowtok[row0 + arow] * HH;
    auto load_A = [&](int st, int k0) {
        uint32_t so = sb + (uint32_t)(st * ASTG + arow_i * 32 + ahalf * 16);
        cpasync16(so, (const char*)(Ahg + abase + k0) + ahalf * 16);
        asm volatile("cp.async.commit_group;" ::: "memory");
    };

    // B: thread owns row k=tid>>4 (0..15), 8 floats at col (tid&15)*8
    const int bk_r = tid >> 4, bn_r = (tid & 15) * 8;
    const float* Bsrc = We + (size_t)bk_r * BROW + n0 + bn_r;
    float4 br0, br1;
    auto ldg_B = [&](int k0) {
        const float4* p = (const float4*)(Bsrc + (size_t)k0 * BROW);
        br0 = p[0]; br1 = p[1];
    };
    auto sts_B = [&](int st) {
        float vs[8] = {br0.x, br0.y, br0.z, br0.w, br1.x, br1.y, br1.z, br1.w};
        __align__(16) __half hb[8];
#pragma unroll
        for (int i = 0; i < 8; i++) hb[i] = __float2half_rn(vs[i]);
        *(uint4*)(dsm + BBASE + st * BSTG + bk_r * BPITCH + bn_r * 2) = *(uint4*)hb;
    };

    float acc[4][4][4];
#pragma unroll
    for (int a = 0; a < 4; a++)
#pragma unroll
        for (int b = 0; b < 4; b++)
#pragma unroll
            for (int c = 0; c < 4; c++) acc[a][b][c] = 0.f;

    // prologue: A(0..2) in flight; B(0) -> smem; B(1) in regs
    ldg_B(0);
    load_A(0, 0);
    load_A(1, BK);
    load_A(2, 2 * BK);
    sts_B(0);
    ldg_B(BK);
    asm volatile("cp.async.wait_group 2;" ::: "memory");
    __syncthreads();

    for (int ch = 0; ch < NC; ch++) {
        const int stA = ch & 3, stB = ch & 1;
        if (ch + 1 < NC) sts_B(stB ^ 1);            // B(ch+1) regs -> smem
        if (ch + 2 < NC) ldg_B((ch + 2) * BK);      // prefetch B(ch+2)
        if (ch + 3 < NC) load_A((ch + 3) & 3, (ch + 3) * BK);

        uint32_t Ast = sb + (uint32_t)(stA * ASTG);
        uint32_t Bst = sb + (uint32_t)(BBASE + stB * BSTG);
        uint32_t Afh[4][4], Bfh[8];
#pragma unroll
        for (int mi = 0; mi < 4; mi++) {
            uint32_t ad = Ast + (uint32_t)(
                (wm * 64 + mi * 16 + (lane & 15)) * 32 + ((lane >> 4) & 1) * 16);
            ldmx4(Afh[mi], ad);
        }
#pragma unroll
        for (int np = 0; np < 2; np++) {
            int krow = ((lane >> 3) & 1) * 8 + (lane & 7);
            int ncol = wn * 32 + np * 16 + ((lane >> 4) & 1) * 8;
            uint32_t bd = Bst + (uint32_t)(krow * BPITCH + ncol * 2);
            ldmx4t(&Bfh[np * 4], bd);
        }
#pragma unroll
        for (int mi = 0; mi < 4; mi++)
#pragma unroll
            for (int ni = 0; ni < 4; ni++)
                mma16816(acc[mi][ni], Afh[mi], &Bfh[ni * 2]);

        if (ch + 1 < NC) asm volatile("cp.async.wait_group 2;" ::: "memory");
        __syncthreads();
    }

    // ---------------- epilogue ----------------
    __half* hh = (__half*)(g_pool + OFF_HH);
    float* outp = (float*)(g_pool + OFF_OUT);
#pragma unroll
    for (int mi = 0; mi < 4; mi++) {
#pragma unroll
        for (int hr = 0; hr < 2; hr++) {
            int mloc = wm * 64 + mi * 16 + hr * 8 + (lane >> 2);
            if (mloc >= rows) continue;
            if (MODE == 0) {
                size_t base = (size_t)(row0 + mloc) * II + n0 + wn * 32 + (lane & 3) * 2;
#pragma unroll
                for (int ni = 0; ni < 4; ni++) {
                    float v0 = acc[mi][ni][hr * 2 + 0];
                    float v1 = acc[mi][ni][hr * 2 + 1];
                    float t0 = 0.7978845608028654f * (v0 + 0.044715f * v0 * v0 * v0);
                    float t1 = 0.7978845608028654f * (v1 + 0.044715f * v1 * v1 * v1);
                    float g0 = 0.5f * v0 * (1.f + tanhf(t0));
                    float g1 = 0.5f * v1 * (1.f + tanhf(t1));
                    __half2 h;
                    h.x = __float2half_rn(g0);
                    h.y = __float2half_rn(g1);
                    *(__half2*)&hh[base + ni * 8] = h;
                }
            } else {
                float w = g_rw[row0 + mloc];
                size_t base = (size_t)(row0 + mloc) * HH + n0 + wn * 32 + (lane & 3) * 2;
#pragma unroll
                for (int ni = 0; ni < 4; ni++) {
                    float2 o;
                    o.x = acc[mi][ni][hr * 2 + 0] * w;
                    o.y = acc[mi][ni][hr * 2 + 1] * w;
                    *(float2*)&outp[base + ni * 8] = o;
                }
            }
        }
    }
}

// ---------------- combine ----------------
__global__ void combine_kernel(float* __restrict__ y) {
    int idx = blockIdx.x * blockDim.x + threadIdx.x;
    int t = idx >> 9, c4 = idx & 511;
    const float4* o = (const float4*)(g_pool + OFF_OUT);
    int p0 = g_pos[t * 2], p1 = g_pos[t * 2 + 1];
    float4 v0 = o[(size_t)p0 * 512 + c4];
    float4 v1 = o[(size_t)p1 * 512 + c4];
    float4 r;
    r.x = v0.x + v1.x; r.y = v0.y + v1.y;
    r.z = v0.z + v1.z; r.w = v0.w + v1.w;
    ((float4*)y)[idx] = r;
}

// ---------------- launch ----------------
extern "C" void kernel_launch(void* const* d_in, const int* in_sizes, int n_in,
                              void* d_out, int out_size) {
    const float* x  = (const float*)d_in[0];
    const float* rw = (const float*)d_in[1];
    const float* w1 = (const float*)d_in[2];
    const float* w2 = (const float*)d_in[3];
    float* y = (float*)d_out;

    cudaFuncSetAttribute(moe_mma_kernel<0>,
                         cudaFuncAttributeMaxDynamicSharedMemorySize, SMEM_DYN);
    cudaFuncSetAttribute(moe_mma_kernel<1>,
                         cudaFuncAttributeMaxDynamicSharedMemorySize, SMEM_DYN);

    convert_x_kernel<<<(TT * HH / 4) / 256, 256>>>(x);        // 1 (also inits)
    router_kernel<<<TT / 8, 256>>>(x, rw);                    // 2
    build_scatter_kernel<<<1, 256>>>(y, (long long)out_size); // 3
    moe_mma_kernel<0><<<dim3(II / 128, 136), 256, SMEM_DYN>>>(w1);  // 4 <- ncu slot
    moe_mma_kernel<1><<<dim3(HH / 128, 136), 256, SMEM_DYN>>>(w2);  // 5
    combine_kernel<<<(TT * HH / 4) / 256, 256>>>(y);          // 6
}

// round 16
// speedup vs baseline: 2.8591x; 1.1040x over previous
#include <cuda_runtime.h>
#include <cuda_fp16.h>
#include <cstdint>

#define TT 8192
#define HH 2048
#define II 4096
#define EE 8
#define TK (TT*2)
#define MAXTILES 144
#define BM 128
#define BK 16

// smem: 4 stages x 8448 (A 4096 pitch-32 | B 4352 pitch-272)
#define STG   8448
#define BOFF  4096
#define BPITCH 272
#define SMEM_DYN (4*STG)

// ---- pool (416MB statics; ~1GB breaks module load — R4/R5 lesson) ----
#define OFF_H   0ULL                 // h fp16 [TK][II]           134MB
#define OFF_X   134217728ULL         // x fp16 [TT][HH]            32MB
#define OFF_W1  167772160ULL         // w1 fp16 [E][HH][II]       128MB
#define OFF_W2  301989888ULL         // w2 fp16 [E][II][HH]       128MB
#define OFF_OUT 134217728ULL         // out fp32 [TK][HH] overlays x+w1 (dead in GEMM2)
#define POOL_BYTES 436207616ULL

__device__ char g_pool[POOL_BYTES];
__device__ int   g_topi[TK];
__device__ float g_topw[TK];
__device__ int   g_rowtok[TK];
__device__ float g_rw[TK];
__device__ int   g_pos[TK];
__device__ int   g_counts[EE];
__device__ int   g_offsets[EE + 1];
__device__ int   g_fill[EE];
__device__ int   g_tile_e[MAXTILES];
__device__ int   g_tile_row[MAXTILES];
__device__ int   g_tile_rows[MAXTILES];
__device__ int   g_num_tiles;

// ---------------- PTX helpers (sm_80 baseline ISA) ----------------
__device__ __forceinline__ uint32_t smem_u32(const void* p) {
    uint32_t a;
    asm("{ .reg .u64 t; cvta.to.shared.u64 t, %1; cvt.u32.u64 %0, t; }"
        : "=r"(a) : "l"(p));
    return a;
}
__device__ __forceinline__ void cpasync16(uint32_t dst, const void* src) {
    asm volatile("cp.async.cg.shared.global [%0], [%1], 16;"
                 :: "r"(dst), "l"(src) : "memory");
}
__device__ __forceinline__ void ldmx4(uint32_t* r, uint32_t addr) {
    asm volatile("ldmatrix.sync.aligned.m8n8.x4.shared.b16 {%0,%1,%2,%3}, [%4];"
                 : "=r"(r[0]), "=r"(r[1]), "=r"(r[2]), "=r"(r[3]) : "r"(addr));
}
__device__ __forceinline__ void ldmx4t(uint32_t* r, uint32_t addr) {
    asm volatile("ldmatrix.sync.aligned.m8n8.x4.trans.shared.b16 {%0,%1,%2,%3}, [%4];"
                 : "=r"(r[0]), "=r"(r[1]), "=r"(r[2]), "=r"(r[3]) : "r"(addr));
}
__device__ __forceinline__ void mma16816(float* d, const uint32_t* a,
                                         const uint32_t* b) {
    asm volatile(
        "mma.sync.aligned.m16n8k16.row.col.f32.f16.f16.f32 "
        "{%0,%1,%2,%3}, {%4,%5,%6,%7}, {%8,%9}, {%0,%1,%2,%3};"
        : "+f"(d[0]), "+f"(d[1]), "+f"(d[2]), "+f"(d[3])
        : "r"(a[0]), "r"(a[1]), "r"(a[2]), "r"(a[3]), "r"(b[0]), "r"(b[1]));
}

// ---------------- x -> fp16 (+ counter init in block 0) --------------------
__global__ void convert_x_kernel(const float* __restrict__ x) {
    if (blockIdx.x == 0 && threadIdx.x < 32) {
        int t = threadIdx.x;
        if (t < EE) { g_counts[t] = 0; g_fill[t] = 0; }
        if (t == 0) g_num_tiles = 0;
    }
    int i = blockIdx.x * blockDim.x + threadIdx.x;
    float4 v = ((const float4*)x)[i];
    __half2 h0, h1;
    h0.x = __float2half_rn(v.x); h0.y = __float2half_rn(v.y);
    h1.x = __float2half_rn(v.z); h1.y = __float2half_rn(v.w);
    __half2* oh = (__half2*)(g_pool + OFF_X);
    oh[i * 2] = h0; oh[i * 2 + 1] = h1;
}

// ---------------- W -> fp16 (dst resolved in DEVICE code) ------------------
template <int MODE>
__global__ void convert_w_kernel(const float* __restrict__ W) {
    size_t i = (size_t)blockIdx.x * blockDim.x + threadIdx.x;  // float4 index
    float4 v = ((const float4*)W)[i];
    __half2 h0, h1;
    h0.x = __float2half_rn(v.x); h0.y = __float2half_rn(v.y);
    h1.x = __float2half_rn(v.z); h1.y = __float2half_rn(v.w);
    __half2* oh = (__half2*)(g_pool + (MODE ? OFF_W2 : OFF_W1));
    oh[i * 2] = h0; oh[i * 2 + 1] = h1;
}

// ---------------- router (proven) ----------------
__global__ void router_kernel(const float* __restrict__ x,
                              const float* __restrict__ rw) {
    int warp = (blockIdx.x * blockDim.x + threadIdx.x) >> 5;
    int lane = threadIdx.x & 31;
    if (warp >= TT) return;
    const float* xr = x + (size_t)warp * HH;
    float acc[EE];
#pragma unroll
    for (int e = 0; e < EE; e++) acc[e] = 0.f;
    for (int i = lane * 4; i < HH; i += 128) {
        float4 xv = *(const float4*)&xr[i];
#pragma unroll
        for (int e = 0; e < EE; e++) {
            float4 wv = *(const float4*)&rw[e * HH + i];
            acc[e] += xv.x * wv.x + xv.y * wv.y + xv.z * wv.z + xv.w * wv.w;
        }
    }
#pragma unroll
    for (int e = 0; e < EE; e++)
#pragma unroll
        for (int off = 16; off; off >>= 1)
            acc[e] += __shfl_xor_sync(0xffffffffu, acc[e], off);
    if (lane == 0) {
        float mx = acc[0];
#pragma unroll
        for (int e = 1; e < EE; e++) mx = fmaxf(mx, acc[e]);
        float p[EE], s = 0.f;
#pragma unroll
        for (int e = 0; e < EE; e++) { p[e] = expf(acc[e] - mx); s += p[e]; }
        float inv = 1.f / s;
        int i1 = 0; float v1 = p[0];
#pragma unroll
        for (int e = 1; e < EE; e++) if (p[e] > v1) { v1 = p[e]; i1 = e; }
        int i2 = -1; float v2 = -1.f;
#pragma unroll
        for (int e = 0; e < EE; e++)
            if (e != i1 && p[e] > v2) { v2 = p[e]; i2 = e; }
        g_topi[warp * 2]     = i1; g_topw[warp * 2]     = v1 * inv;
        g_topi[warp * 2 + 1] = i2; g_topw[warp * 2 + 1] = v2 * inv;
        atomicAdd(&g_counts[i1], 1);
        atomicAdd(&g_counts[i2], 1);
    }
}

// ---------------- build offsets + tiles, then scatter (merged) -------------
__global__ void build_scatter_kernel(float* d_out, long long out_size) {
    int tid = threadIdx.x;
    if (tid == 0) {
        int off = 0;
        for (int e = 0; e < EE; e++) { g_offsets[e] = off; off += g_counts[e]; }
        g_offsets[EE] = off;
        int nt = 0;
        for (int e = 0; e < EE; e++) {
            int n = g_counts[e];
            for (int j = 0; j < n; j += BM) {
                g_tile_e[nt]    = e;
                g_tile_row[nt]  = g_offsets[e] + j;
                g_tile_rows[nt] = (n - j < BM) ? (n - j) : BM;
                nt++;
            }
        }
        g_num_tiles = nt;
        long long base = (long long)TT * HH;
        long long extra = out_size - base;
        for (long long i = 0; i < extra; i++)
            d_out[base + i] = (i < EE) ? (float)g_counts[i] : 0.f;
    }
    __syncthreads();
    for (int i = tid; i < TK; i += blockDim.x) {
        int e = g_topi[i];
        int p = g_offsets[e] + atomicAdd(&g_fill[e], 1);
        g_rowtok[p] = i >> 1;
        g_rw[p]     = g_topw[i];
        g_pos[i]    = p;
    }
}

// ---------------- grouped GEMM: fp16, all-cp.async, RACE-FREE tail ---------
// MODE 0: h = gelu(xs @ w1)   MODE 1: out = rw*(h @ w2)
// Warp grid 2(m) x 4(n), warp tile 64x32 (R7-proven fragment mapping).
template <int MODE>
__global__ __launch_bounds__(256, 2) void moe_mma_kernel() {
    const int KLEN = MODE ? II : HH;
    const int BROW = MODE ? HH : II;
    const int NC = KLEN / BK;
    int tile = blockIdx.y;
    if (tile >= g_num_tiles) return;
    const int e = g_tile_e[tile], row0 = g_tile_row[tile], rows = g_tile_rows[tile];
    const int n0 = blockIdx.x * 128;
    const int tid = threadIdx.x, wid = tid >> 5, lane = tid & 31;
    const int wm = wid & 1, wn = wid >> 1;   // 64(m) x 32(n) warp tile

    extern __shared__ __align__(128) char dsm[];
    uint32_t sb = smem_u32(dsm);

    const __half* Ahg = (const __half*)(g_pool + (MODE ? OFF_H : OFF_X));
    const __half* Whe = (const __half*)(g_pool + (MODE ? OFF_W2 : OFF_W1)) +
                        (size_t)e * KLEN * BROW + n0;

    // A: thread pair per row (16 fp16 = 32B per row; each thread 16B)
    const int arow_i = tid >> 1, ahalf = tid & 1;
    const int arow = (arow_i < rows) ? arow_i : (rows - 1);
    const size_t abase = MODE ? (size_t)(row0 + arow) * II
                              : (size_t)g_rowtok[row0 + arow] * HH;
    // B: thread owns row bk=tid>>4 (0..15), 16B seg bseg=tid&15
    const int bk = tid >> 4, bseg = tid & 15;

    auto load_AB = [&](int st, int k0) {
        uint32_t so = sb + (uint32_t)(st * STG);
        cpasync16(so + arow_i * 32 + ahalf * 16,
                  (const char*)(Ahg + abase + k0) + ahalf * 16);
        cpasync16(so + BOFF + bk * BPITCH + bseg * 16,
                  (const char*)(Whe + (size_t)(k0 + bk) * BROW) + bseg * 16);
        asm volatile("cp.async.commit_group;" ::: "memory");
    };

    float acc[4][4][4];
#pragma unroll
    for (int a = 0; a < 4; a++)
#pragma unroll
        for (int b = 0; b < 4; b++)
#pragma unroll
            for (int c = 0; c < 4; c++) acc[a][b][c] = 0.f;

    // prologue: stages 0..2 in flight; wait -> G0 complete
    load_AB(0, 0);
    load_AB(1, BK);
    load_AB(2, 2 * BK);
    asm volatile("cp.async.wait_group 2;" ::: "memory");
    __syncthreads();

    for (int ch = 0; ch < NC; ch++) {
        const int st = ch & 3;
        if (ch + 3 < NC) load_AB((ch + 3) & 3, (ch + 3) * BK);

        uint32_t Ast = sb + (uint32_t)(st * STG);
        uint32_t Afh[4][4], Bfh[8];
#pragma unroll
        for (int mi = 0; mi < 4; mi++) {
            uint32_t ad = Ast + (uint32_t)(
                (wm * 64 + mi * 16 + (lane & 15)) * 32 + ((lane >> 4) & 1) * 16);
            ldmx4(Afh[mi], ad);
        }
#pragma unroll
        for (int np = 0; np < 2; np++) {
            int krow = ((lane >> 3) & 1) * 8 + (lane & 7);
            int ncol = wn * 32 + np * 16 + ((lane >> 4) & 1) * 8;
            uint32_t bd = Ast + (uint32_t)(BOFF + krow * BPITCH + ncol * 2);
            ldmx4t(&Bfh[np * 4], bd);
        }
#pragma unroll
        for (int mi = 0; mi < 4; mi++)
#pragma unroll
            for (int ni = 0; ni < 4; ni++)
                mma16816(acc[mi][ni], Afh[mi], &Bfh[ni * 2]);

        // End-of-iter wait must make group G(ch+1) (next stage) complete:
        //  committed so far = min(NC, ch+4).
        if (ch + 1 < NC) {
            if (ch + 4 <= NC)
                asm volatile("cp.async.wait_group 2;" ::: "memory");
            else if (ch + 3 == NC)
                asm volatile("cp.async.wait_group 1;" ::: "memory");
            else
                asm volatile("cp.async.wait_group 0;" ::: "memory");
            __syncthreads();
        }
    }

    // ---------------- epilogue ----------------
    __half* hh = (__half*)(g_pool + OFF_H);
    float* outp = (float*)(g_pool + OFF_OUT);
#pragma unroll
    for (int mi = 0; mi < 4; mi++) {
#pragma unroll
        for (int hr = 0; hr < 2; hr++) {
            int mloc = wm * 64 + mi * 16 + hr * 8 + (lane >> 2);
            if (mloc >= rows) continue;
            if (MODE == 0) {
                size_t base = (size_t)(row0 + mloc) * II + n0 + wn * 32 + (lane & 3) * 2;
#pragma unroll
                for (int ni = 0; ni < 4; ni++) {
                    float v0 = acc[mi][ni][hr * 2 + 0];
                    float v1 = acc[mi][ni][hr * 2 + 1];
                    float t0 = 0.7978845608028654f * (v0 + 0.044715f * v0 * v0 * v0);
                    float t1 = 0.7978845608028654f * (v1 + 0.044715f * v1 * v1 * v1);
                    float g0 = 0.5f * v0 * (1.f + tanhf(t0));
                    float g1 = 0.5f * v1 * (1.f + tanhf(t1));
                    __half2 h;
                    h.x = __float2half_rn(g0);
                    h.y = __float2half_rn(g1);
                    *(__half2*)&hh[base + ni * 8] = h;
                }
            } else {
                float w = g_rw[row0 + mloc];
                size_t base = (size_t)(row0 + mloc) * HH + n0 + wn * 32 + (lane & 3) * 2;
#pragma unroll
                for (int ni = 0; ni < 4; ni++) {
                    float2 o;
                    o.x = acc[mi][ni][hr * 2 + 0] * w;
                    o.y = acc[mi][ni][hr * 2 + 1] * w;
                    *(float2*)&outp[base + ni * 8] = o;
                }
            }
        }
    }
}

// ---------------- combine ----------------
__global__ void combine_kernel(float* __restrict__ y) {
    int idx = blockIdx.x * blockDim.x + threadIdx.x;
    int t = idx >> 9, c4 = idx & 511;
    const float4* o = (const float4*)(g_pool + OFF_OUT);
    int p0 = g_pos[t * 2], p1 = g_pos[t * 2 + 1];
    float4 v0 = o[(size_t)p0 * 512 + c4];
    float4 v1 = o[(size_t)p1 * 512 + c4];
    float4 r;
    r.x = v0.x + v1.x; r.y = v0.y + v1.y;
    r.z = v0.z + v1.z; r.w = v0.w + v1.w;
    ((float4*)y)[idx] = r;
}

// ---------------- launch ----------------
extern "C" void kernel_launch(void* const* d_in, const int* in_sizes, int n_in,
                              void* d_out, int out_size) {
    const float* x  = (const float*)d_in[0];
    const float* rw = (const float*)d_in[1];
    const float* w1 = (const float*)d_in[2];
    const float* w2 = (const float*)d_in[3];
    float* y = (float*)d_out;

    cudaFuncSetAttribute(moe_mma_kernel<0>,
                         cudaFuncAttributeMaxDynamicSharedMemorySize, SMEM_DYN);
    cudaFuncSetAttribute(moe_mma_kernel<1>,
                         cudaFuncAttributeMaxDynamicSharedMemorySize, SMEM_DYN);

    convert_x_kernel<<<(TT * HH / 4) / 256, 256>>>(x);            // 1 (+init)
    router_kernel<<<TT / 8, 256>>>(x, rw);                        // 2
    build_scatter_kernel<<<1, 256>>>(y, (long long)out_size);     // 3
    convert_w_kernel<0><<<(EE * HH * II / 4) / 256, 256>>>(w1);   // 4
    convert_w_kernel<1><<<(EE * II * HH / 4) / 256, 256>>>(w2);   // 5
    moe_mma_kernel<0><<<dim3(II / 128, 136), 256, SMEM_DYN>>>();  // 6
    moe_mma_kernel<1><<<dim3(HH / 128, 136), 256, SMEM_DYN>>>();  // 7
    combine_kernel<<<(TT * HH / 4) / 256, 256>>>(y);              // 8
}